// round 6
// baseline (speedup 1.0000x reference)
#include <cuda_runtime.h>
#include <math.h>

#define NN 50000
#define NE 800000
#define EPSV 1e-5

// ---------------- fp64 scratch (__device__ globals; no runtime alloc) ----------------
__device__ double g_degd[NN];
__device__ double g_normwd[NE];
__device__ double g_Ed[NN * 64];
__device__ double g_hlind[NN * 64];
__device__ double g_hcatd[NN * 192];
__device__ double g_hcatnd[NN * 192];
__device__ double g_ssmd[NN * 16];
__device__ double g_ac_embd[128];
__device__ double g_ac_g0d[128];
__device__ double g_ac_g1d[128];
__device__ double g_ac_gld[384];
__device__ double g_embd[256 * 3088];
__device__ double g_h1d[256 * 128];
__device__ double g_h2d[256 * 128];
__device__ double g_h3d[256 * 128];
__device__ double g_h1pred[256 * 128];
__device__ float  g_sub2f[16 * 256];   // fp32 sort keys (this round's experiment)

// fp64 accumulator zone (memset to 0 once per launch)
#define D_EMB    0      // 128
#define D_G0     128    // 128
#define D_G1     256    // 128
#define D_GL     384    // 384
#define D_COLSUM 768    // 16
#define D_SS     784    // 256
#define D_NUM    1040   // 1
#define D_DEN    1041   // 1
#define D_OUT    1048   // 3072
#define D_TOTAL  4120
__device__ double g_d[D_TOTAL];

__device__ __forceinline__ void redd(double* p, double v) {
    asm volatile("red.global.add.f64 [%0], %1;" :: "l"(p), "d"(v) : "memory");
}

// ---------------- kernels ----------------

__global__ void k_deg(const int* ei, const float* ew) {
    int e = blockIdx.x * blockDim.x + threadIdx.x;
    if (e < NE) atomicAdd(&g_degd[ei[e]], (double)ew[e]);
}

__global__ void k_norm(const int* ei, const float* ew) {
    int e = blockIdx.x * blockDim.x + threadIdx.x;
    if (e < NE) {
        double d = g_degd[ei[e]];
        if (d < 0.5) d += 1.0;
        g_normwd[e] = (double)ew[e] / d;
    }
}

// embedding gather + per-channel sum/sumsq (fp64)
__global__ void k_embed(const int* x, const float* tab) {
    int c = threadIdx.x & 63;
    int rbase = blockIdx.x * 4 + (threadIdx.x >> 6);
    double s = 0.0, s2 = 0.0;
    for (int r = rbase; r < NN; r += gridDim.x * 4) {
        double v = (double)tab[x[r] * 64 + c];
        g_Ed[r * 64 + c] = v;
        s += v; s2 += v * v;
    }
    atomicAdd(&g_d[D_EMB + c], s);
    atomicAdd(&g_d[D_EMB + 64 + c], s2);
}

// per-channel sum/sumsq over a column slice of fp64 matrix
__global__ void k_gnsum(const double* x, int ld, int C, double* sums) {
    int c = threadIdx.x;   // blockDim.x == C
    double s = 0.0, s2 = 0.0;
    for (int r = blockIdx.x; r < NN; r += gridDim.x) {
        double v = x[r * ld + c];
        s += v; s2 += v * v;
    }
    atomicAdd(&sums[c], s);
    atomicAdd(&sums[C + c], s2);
}

// GraphNorm -> per-channel affine y = a*x + c  (all fp64)
__global__ void k_affine(const double* sums, const float* w, const float* b,
                         const float* ms, double* ac, int C, double invN) {
    int c = blockIdx.x * blockDim.x + threadIdx.x;
    if (c < C) {
        double mu = sums[c] * invN;
        double ex2 = sums[C + c] * invN;
        double m = (double)ms[c];
        double var = ex2 - 2.0 * m * mu * mu + m * m * mu * mu;
        double a = (double)w[c] / sqrt(var + EPSV);
        ac[c] = a;
        ac[C + c] = (double)b[c] - a * m * mu;
    }
}

// node Linear (fp64): out = relu( f(in)*W + b ), f = affine (+optional relu)
__global__ void k_lin(const double* in, int ldin, const double* ac, int prerelu,
                      const float* W, const float* bias) {
    __shared__ double Xs[32][65];
    __shared__ float  Ws[64][64];
    __shared__ double as_[64], cs_[64], bs_[64];
    int tid = threadIdx.x;
    for (int i = tid; i < 4096; i += 256) Ws[i >> 6][i & 63] = W[i];
    if (tid < 64) { as_[tid] = ac[tid]; cs_[tid] = ac[64 + tid]; bs_[tid] = (double)bias[tid]; }
    __syncthreads();
    int r0 = blockIdx.x * 32;
    for (int i = tid; i < 2048; i += 256) {
        int r = i >> 6, c = i & 63;
        int gr = r0 + r;
        double v = 0.0;
        if (gr < NN) {
            v = as_[c] * in[gr * ldin + c] + cs_[c];
            if (prerelu) v = fmax(v, 0.0);
        }
        Xs[r][c] = v;
    }
    __syncthreads();
    int c = (tid & 15) * 4, rr = (tid >> 4) * 2;
    double acc[2][4] = {};
    for (int k = 0; k < 64; k++) {
        double w0 = (double)Ws[k][c + 0];
        double w1 = (double)Ws[k][c + 1];
        double w2 = (double)Ws[k][c + 2];
        double w3 = (double)Ws[k][c + 3];
        #pragma unroll
        for (int i = 0; i < 2; i++) {
            double xv = Xs[rr + i][k];
            acc[i][0] += xv * w0; acc[i][1] += xv * w1;
            acc[i][2] += xv * w2; acc[i][3] += xv * w3;
        }
    }
    for (int i = 0; i < 2; i++) {
        int gr = r0 + rr + i;
        if (gr < NN) {
            #pragma unroll
            for (int j = 0; j < 4; j++)
                g_hlind[gr * 64 + c + j] = fmax(acc[i][j] + bs_[c + j], 0.0);
        }
    }
}

// SpMM fp64: hcat[row, coloff:] += norm_w * hlin[col]; 16 threads/edge, 4 ch each
__global__ void k_spmm(const int* ei, int coloff) {
    long long total = (long long)NE * 16;
    for (long long t = (long long)blockIdx.x * blockDim.x + threadIdx.x; t < total;
         t += (long long)gridDim.x * blockDim.x) {
        int e = (int)(t >> 4), j = (int)(t & 15);
        int c = ei[NE + e];
        double w = g_normwd[e];
        int r = ei[e];
        const double* src = &g_hlind[c * 64 + j * 4];
        double* dst = &g_hcatd[r * 192 + coloff + j * 4];
        #pragma unroll
        for (int q = 0; q < 4; q++) redd(dst + q, w * src[q]);
    }
}

// materialize normalized concat: hcatn = a_f*hcat + c_f
__global__ void k_normcat() {
    int r = blockIdx.x, f = threadIdx.x;   // <<<NN, 192>>>
    int idx = r * 192 + f;
    g_hcatnd[idx] = g_ac_gld[f] * g_hcatd[idx] + g_ac_gld[192 + f];
}

// s = hcatn @ sW + sb (fp64), softmax; fused: colsum, ss, mincut_den
__global__ void k_soft(const float* sW, const float* sb) {
    __shared__ double H[16][193];
    __shared__ float  Ws[3072];
    __shared__ double Sm[16][17];
    __shared__ float  sbs[16];
    int t = threadIdx.x;
    for (int i = t; i < 3072; i += 256) Ws[i] = sW[i];
    if (t < 16) sbs[t] = sb[t];
    int i_ = t >> 4, k_ = t & 15;
    double ss_acc = 0.0, col_acc = 0.0, den_acc = 0.0;
    for (int tile = blockIdx.x; tile < 3125; tile += gridDim.x) {
        int n0 = tile * 16;
        __syncthreads();
        for (int i = t; i < 16 * 192; i += 256) {
            int r = i / 192, f = i - r * 192;
            H[r][f] = g_hcatnd[(n0 + r) * 192 + f];
        }
        __syncthreads();
        {
            double acc = 0.0;
            for (int f = 0; f < 192; f++) acc += H[i_][f] * (double)Ws[f * 16 + k_];
            Sm[i_][k_] = acc + (double)sbs[k_];
        }
        __syncthreads();
        if (t < 16) {
            int gr = n0 + t;
            double mx = -1e300;
            #pragma unroll
            for (int j = 0; j < 16; j++) mx = fmax(mx, Sm[t][j]);
            double ev[16]; double s = 0.0;
            #pragma unroll
            for (int j = 0; j < 16; j++) { ev[j] = exp(Sm[t][j] - mx); s += ev[j]; }
            double inv = 1.0 / s;
            double sq = 0.0;
            #pragma unroll
            for (int j = 0; j < 16; j++) {
                double v = ev[j] * inv;
                Sm[t][j] = v;
                g_ssmd[gr * 16 + j] = v;
                sq += v * v;
            }
            den_acc += g_degd[gr] * sq;
        }
        __syncthreads();
        {
            double s = 0.0;
            #pragma unroll
            for (int i = 0; i < 16; i++) s += Sm[i][i_] * Sm[i][k_];
            ss_acc += s;
        }
        if (t < 16) {
            double s = 0.0;
            #pragma unroll
            for (int i = 0; i < 16; i++) s += Sm[i][t];
            col_acc += s;
        }
    }
    atomicAdd(&g_d[D_SS + t], ss_acc);
    if (t < 16) atomicAdd(&g_d[D_COLSUM + t], col_acc);
    if (t < 16) atomicAdd(&g_d[D_DEN], den_acc);
}

// mincut numerator: sum_e w[e] * <s_sm[row], s_sm[col]>  (fp64)
__global__ void k_num(const int* ei, const float* ew) {
    double acc = 0.0;
    for (int e = blockIdx.x * blockDim.x + threadIdx.x; e < NE;
         e += gridDim.x * blockDim.x) {
        int r = ei[e], c = ei[NE + e];
        const double* a = &g_ssmd[r * 16];
        const double* b = &g_ssmd[c * 16];
        double d = 0.0;
        #pragma unroll
        for (int i = 0; i < 16; i++) d += a[i] * b[i];
        acc += (double)ew[e] * d;
    }
    __shared__ double red[256];
    red[threadIdx.x] = acc; __syncthreads();
    for (int s = 128; s > 0; s >>= 1) {
        if (threadIdx.x < s) red[threadIdx.x] += red[threadIdx.x + s];
        __syncthreads();
    }
    if (threadIdx.x == 0) atomicAdd(&g_d[D_NUM], red[0]);
}

// out[k,f] = sum_n s_sm[n,k]*hcatn[n,f]  (fp64, persistent n-split)
__global__ void k_poolout() {
    __shared__ double Hs[8][193];
    __shared__ double Ss[8][16];
    int t = threadIdx.x;
    int k = t & 15, fb = (t >> 4) * 12;
    double acc[12];
    #pragma unroll
    for (int j = 0; j < 12; j++) acc[j] = 0.0;
    for (int tile = blockIdx.x; tile < 6250; tile += gridDim.x) {
        int r0 = tile * 8;
        __syncthreads();
        for (int i = t; i < 8 * 192; i += 256) {
            int r = i / 192, f = i - r * 192;
            Hs[r][f] = g_hcatnd[(r0 + r) * 192 + f];
        }
        if (t < 128) Ss[t >> 4][t & 15] = g_ssmd[(r0 + (t >> 4)) * 16 + (t & 15)];
        __syncthreads();
        #pragma unroll
        for (int i = 0; i < 8; i++) {
            double sv = Ss[i][k];
            #pragma unroll
            for (int j = 0; j < 12; j++) acc[j] += sv * Hs[i][fb + j];
        }
    }
    for (int j = 0; j < 12; j++)
        atomicAdd(&g_d[D_OUT + k * 192 + fb + j], acc[j]);
}

// ======= EXPERIMENT: sub2 sort keys in fp32, sequential 16-lane accumulation =======
// sub2[k,m] = sum_n (s_sm[n,k]/colsum_k) * SA[m,n], computed entirely in fp32 with
// a natural interleaved-lane order (mimicking a vectorized fp32 reduction).
__global__ void k_sub2f32(const float* SA) {
    __shared__ float lred[16][17];
    int m = blockIdx.x;          // 256 blocks, one per subgraph
    int t = threadIdx.x;         // 256 threads: k = t>>4, lane = t&15
    int k = t >> 4, lane = t & 15;
    float cs = (float)g_d[D_COLSUM + k];
    if (cs < 1e-12f) cs = 1e-12f;
    float acc = 0.f;
    const float* sa = SA + (size_t)m * NN;
    for (int n = lane; n < NN; n += 16) {
        float sv = (float)g_ssmd[n * 16 + k];
        float tv = sv / cs;                 // ref: t = s_sm.T / colsum (fp32 divide)
        acc = fmaf(tv, sa[n], acc);
    }
    lred[k][lane] = acc;
    __syncthreads();
    for (int s = 8; s > 0; s >>= 1) {       // pairwise lane reduce (fp32)
        if (lane < s) lred[k][lane] += lred[k][lane + s];
        __syncthreads();
    }
    if (lane == 0) g_sub2f[k * 256 + m] = lred[k][0];
}

// losses (fp64)
__global__ void k_fin(float* dout) {
    int t = threadIdx.x;
    __shared__ double red[256];
    __shared__ double fro;
    double v = g_d[D_SS + t];
    red[t] = v * v; __syncthreads();
    for (int s = 128; s > 0; s >>= 1) { if (t < s) red[t] += red[t + s]; __syncthreads(); }
    if (t == 0) fro = sqrt(red[0]);
    __syncthreads();
    double d = v / fro - (((t >> 4) == (t & 15)) ? 0.25 : 0.0);
    red[t] = d * d; __syncthreads();
    for (int s = 128; s > 0; s >>= 1) { if (t < s) red[t] += red[t + s]; __syncthreads(); }
    if (t == 0) {
        dout[16385] = (float)sqrt(red[0]);
        dout[16384] = (float)(-(g_d[D_NUM] / g_d[D_DEN]));
    }
}

// per-subgraph: stable sort clusters by fp32 score desc, emit emb row
__global__ void k_embbuild() {
    __shared__ float rs[16];
    __shared__ int perm[16];
    int m = blockIdx.x, t = threadIdx.x;
    if (t < 16) rs[t] = g_sub2f[t * 256 + m];
    __syncthreads();
    if (t == 0) {
        int p[16];
        for (int i = 0; i < 16; i++) p[i] = i;
        for (int i = 1; i < 16; i++) {
            int key = p[i]; float kv = rs[key];
            int j = i - 1;
            while (j >= 0 && rs[p[j]] < kv) { p[j + 1] = p[j]; j--; }
            p[j + 1] = key;
        }
        for (int i = 0; i < 16; i++) perm[i] = p[i];
    }
    __syncthreads();
    for (int idx = t; idx < 3088; idx += 256) {
        int j = idx / 193, f = idx - j * 193;
        int pk = perm[j];
        g_embd[m * 3088 + idx] = (f < 192) ? g_d[D_OUT + pk * 192 + f] : (double)rs[pk];
    }
}

// MLP layer 1: 256x3088 @ 3088x128 (fp64), split-K=16 with fp64 atomics
__global__ void k_mlp1(const float* W1) {
    int b = blockIdx.x;
    int rt = b & 7; b >>= 3; int ct = b & 1; int ks = b >> 1;
    int r0 = rt * 32, c0 = ct * 64, k0 = ks * 193;
    __shared__ double As[32][33];
    __shared__ float  Bs[32][64];
    int t = threadIdx.x;
    int c = (t & 15) * 4, rr = (t >> 4) * 2;
    double acc[2][4] = {};
    for (int kk = 0; kk < 193; kk += 32) {
        int kc = 193 - kk; if (kc > 32) kc = 32;
        for (int i = t; i < 32 * 32; i += 256) {
            int r = i >> 5, kx = i & 31;
            As[r][kx] = (kx < kc) ? g_embd[(r0 + r) * 3088 + k0 + kk + kx] : 0.0;
        }
        for (int i = t; i < 32 * 64; i += 256) {
            int kx = i >> 6, cc = i & 63;
            Bs[kx][cc] = (kx < kc) ? W1[(k0 + kk + kx) * 128 + c0 + cc] : 0.f;
        }
        __syncthreads();
        #pragma unroll 8
        for (int kx = 0; kx < 32; kx++) {
            double b0 = (double)Bs[kx][c + 0], b1 = (double)Bs[kx][c + 1];
            double b2 = (double)Bs[kx][c + 2], b3 = (double)Bs[kx][c + 3];
            double a0 = As[rr][kx], a1 = As[rr + 1][kx];
            acc[0][0] += a0 * b0; acc[0][1] += a0 * b1;
            acc[0][2] += a0 * b2; acc[0][3] += a0 * b3;
            acc[1][0] += a1 * b0; acc[1][1] += a1 * b1;
            acc[1][2] += a1 * b2; acc[1][3] += a1 * b3;
        }
        __syncthreads();
    }
    for (int i = 0; i < 2; i++)
        for (int j = 0; j < 4; j++)
            atomicAdd(&g_h1pred[(r0 + rr + i) * 128 + c0 + c + j], acc[i][j]);
}

__global__ void k_biasrelu(const float* b1) {
    int idx = blockIdx.x * blockDim.x + threadIdx.x;
    if (idx < 256 * 128)
        g_h1d[idx] = fmax(g_h1pred[idx] + (double)b1[idx & 127], 0.0);
}

// small dense layers fp64: 256x128 @ 128xCo
__global__ void k_mlps(const double* in, const float* W, const float* bias,
                       double* outd, float* outf, int Co, int dorelu) {
    __shared__ double As[32][129];
    int r0 = blockIdx.x * 32, c0 = blockIdx.y * 32;
    int t = threadIdx.x;
    for (int i = t; i < 32 * 128; i += 256) {
        int r = i >> 7, kx = i & 127;
        As[r][kx] = in[(r0 + r) * 128 + kx];
    }
    __syncthreads();
    int r = t >> 3, c = (t & 7) * 4;
    double a0 = 0, a1 = 0, a2 = 0, a3 = 0;
    for (int kx = 0; kx < 128; kx++) {
        double a = As[r][kx];
        const float* wrow = &W[kx * Co + c0 + c];
        a0 += a * (double)wrow[0]; a1 += a * (double)wrow[1];
        a2 += a * (double)wrow[2]; a3 += a * (double)wrow[3];
    }
    double o0 = a0 + (double)bias[c0 + c + 0];
    double o1 = a1 + (double)bias[c0 + c + 1];
    double o2 = a2 + (double)bias[c0 + c + 2];
    double o3 = a3 + (double)bias[c0 + c + 3];
    if (dorelu) { o0 = fmax(o0, 0.0); o1 = fmax(o1, 0.0); o2 = fmax(o2, 0.0); o3 = fmax(o3, 0.0); }
    int base = (r0 + r) * Co + c0 + c;
    if (outd) {
        outd[base + 0] = o0; outd[base + 1] = o1;
        outd[base + 2] = o2; outd[base + 3] = o3;
    } else {
        outf[base + 0] = (float)o0; outf[base + 1] = (float)o1;
        outf[base + 2] = (float)o2; outf[base + 3] = (float)o3;
    }
}

// ---------------- launch ----------------
extern "C" void kernel_launch(void* const* d_in, const int* in_sizes, int n_in,
                              void* d_out, int out_size) {
    const int*   x    = (const int*)d_in[0];
    const int*   ei   = (const int*)d_in[1];
    const float* ew   = (const float*)d_in[2];
    const float* SA   = (const float*)d_in[4];
    const float* tab  = (const float*)d_in[5];
    const float* egw  = (const float*)d_in[6];
    const float* egb  = (const float*)d_in[7];
    const float* egm  = (const float*)d_in[8];
    const float* cW   = (const float*)d_in[9];
    const float* cB   = (const float*)d_in[10];
    const float* gnw  = (const float*)d_in[11];
    const float* gnb  = (const float*)d_in[12];
    const float* gnm  = (const float*)d_in[13];
    const float* glw  = (const float*)d_in[14];
    const float* glb  = (const float*)d_in[15];
    const float* glm  = (const float*)d_in[16];
    const float* sW   = (const float*)d_in[17];
    const float* sb   = (const float*)d_in[18];
    const float* pW1  = (const float*)d_in[19];
    const float* pb1  = (const float*)d_in[20];
    const float* pW2  = (const float*)d_in[21];
    const float* pb2  = (const float*)d_in[22];
    const float* pW3  = (const float*)d_in[23];
    const float* pb3  = (const float*)d_in[24];
    const float* pW4  = (const float*)d_in[25];
    const float* pb4  = (const float*)d_in[26];
    float* out = (float*)d_out;

    void *pv;
    double *degd_p, *hcatd_p, *Ed_p, *aced, *ac0d, *ac1d, *acld;
    double *h1d_p, *h2d_p, *h3d_p, *h1pred_p, *d_p;
    cudaGetSymbolAddress(&pv, g_degd);    degd_p  = (double*)pv;
    cudaGetSymbolAddress(&pv, g_hcatd);   hcatd_p = (double*)pv;
    cudaGetSymbolAddress(&pv, g_Ed);      Ed_p    = (double*)pv;
    cudaGetSymbolAddress(&pv, g_ac_embd); aced    = (double*)pv;
    cudaGetSymbolAddress(&pv, g_ac_g0d);  ac0d    = (double*)pv;
    cudaGetSymbolAddress(&pv, g_ac_g1d);  ac1d    = (double*)pv;
    cudaGetSymbolAddress(&pv, g_ac_gld);  acld    = (double*)pv;
    cudaGetSymbolAddress(&pv, g_h1d);     h1d_p   = (double*)pv;
    cudaGetSymbolAddress(&pv, g_h2d);     h2d_p   = (double*)pv;
    cudaGetSymbolAddress(&pv, g_h3d);     h3d_p   = (double*)pv;
    cudaGetSymbolAddress(&pv, g_h1pred);  h1pred_p = (double*)pv;
    cudaGetSymbolAddress(&pv, g_d);       d_p     = (double*)pv;

    cudaMemsetAsync(degd_p, 0, (size_t)NN * 8);
    cudaMemsetAsync(hcatd_p, 0, (size_t)NN * 192 * 8);
    cudaMemsetAsync(h1pred_p, 0, (size_t)256 * 128 * 8);
    cudaMemsetAsync(d_p, 0, (size_t)D_TOTAL * 8);

    const double invN = 1.0 / (double)NN;

    k_deg<<<3125, 256>>>(ei, ew);
    k_norm<<<3125, 256>>>(ei, ew);
    k_embed<<<256, 256>>>(x, tab);
    k_affine<<<1, 256>>>(d_p + D_EMB, egw, egb, egm, aced, 64, invN);

    // layer 0
    k_lin<<<1563, 256>>>(Ed_p, 64, aced, 0, cW, cB);
    k_spmm<<<4096, 256>>>(ei, 0);
    k_gnsum<<<256, 64>>>(hcatd_p, 192, 64, d_p + D_G0);
    k_affine<<<1, 256>>>(d_p + D_G0, gnw, gnb, gnm, ac0d, 64, invN);
    // layer 1
    k_lin<<<1563, 256>>>(hcatd_p, 192, ac0d, 1, cW + 4096, cB + 64);
    k_spmm<<<4096, 256>>>(ei, 64);
    k_gnsum<<<256, 64>>>(hcatd_p + 64, 192, 64, d_p + D_G1);
    k_affine<<<1, 256>>>(d_p + D_G1, gnw + 64, gnb + 64, gnm + 64, ac1d, 64, invN);
    // layer 2
    k_lin<<<1563, 256>>>(hcatd_p + 64, 192, ac1d, 1, cW + 8192, cB + 128);
    k_spmm<<<4096, 256>>>(ei, 128);

    // final GraphNorm over concat -> materialized hcatn (fp64)
    k_gnsum<<<256, 192>>>(hcatd_p, 192, 192, d_p + D_GL);
    k_affine<<<1, 256>>>(d_p + D_GL, glw, glb, glm, acld, 192, invN);
    k_normcat<<<NN, 192>>>();

    k_soft<<<256, 256>>>(sW, sb);
    k_num<<<2048, 256>>>(ei, ew);
    k_poolout<<<256, 256>>>();
    k_sub2f32<<<256, 256>>>(SA);
    k_fin<<<1, 256>>>(out);
    k_embbuild<<<256, 256>>>();

    k_mlp1<<<256, 256>>>(pW1);
    k_biasrelu<<<128, 256>>>(pb1);
    k_mlps<<<dim3(8, 4), 256>>>(h1d_p, pW2, pb2, h2d_p, (float*)0, 128, 1);
    k_mlps<<<dim3(8, 4), 256>>>(h2d_p, pW3, pb3, h3d_p, (float*)0, 128, 1);
    k_mlps<<<dim3(8, 2), 256>>>(h3d_p, pW4, pb4, (double*)0, out, 64, 0);

    (void)in_sizes; (void)n_in; (void)out_size;
}

// round 7
// speedup vs baseline: 1.0425x; 1.0425x over previous
#include <cuda_runtime.h>
#include <math.h>

#define NN 50000
#define NE 800000
#define EPSV 1e-5

// ---------------- fp64 scratch (__device__ globals; no runtime alloc) ----------------
__device__ double g_degd[NN];
__device__ double g_normwd[NE];
__device__ double g_Ed[NN * 64];
__device__ double g_hlind[NN * 64];
__device__ double g_hcatd[NN * 192];
__device__ double g_hcatnd[NN * 192];
__device__ double g_ssmd[NN * 16];
__device__ float  g_ssmf[NN * 16];     // fp32 copy for the sort-key kernel
__device__ double g_ac_embd[128];
__device__ double g_ac_g0d[128];
__device__ double g_ac_g1d[128];
__device__ double g_ac_gld[384];
__device__ double g_embd[256 * 3088];
__device__ double g_h1d[256 * 128];
__device__ double g_h2d[256 * 128];
__device__ double g_h3d[256 * 128];
__device__ double g_h1pred[256 * 128];
__device__ float  g_sub2f[16 * 256];   // fp32 sort keys (winning scheme — DO NOT TOUCH)

// CSR structures (built once per launch)
__device__ int    g_cnt[NN];
__device__ int    g_cur[NN];
__device__ int    g_rowoff[NN + 1];
__device__ int    g_csrc[NE];
__device__ double g_csrw[NE];

// fp64 accumulator zone (memset to 0 once per launch)
#define D_EMB    0      // 128
#define D_G0     128    // 128
#define D_G1     256    // 128
#define D_GL     384    // 384
#define D_COLSUM 768    // 16
#define D_SS     784    // 256
#define D_NUM    1040   // 1
#define D_DEN    1041   // 1
#define D_OUT    1048   // 3072
#define D_TOTAL  4120
__device__ double g_d[D_TOTAL];

// ---------------- kernels ----------------

__global__ void k_deg(const int* ei, const float* ew) {
    int e = blockIdx.x * blockDim.x + threadIdx.x;
    if (e < NE) {
        atomicAdd(&g_degd[ei[e]], (double)ew[e]);
        atomicAdd(&g_cnt[ei[e]], 1);
    }
}

__global__ void k_norm(const int* ei, const float* ew) {
    int e = blockIdx.x * blockDim.x + threadIdx.x;
    if (e < NE) {
        double d = g_degd[ei[e]];
        if (d < 0.5) d += 1.0;
        g_normwd[e] = (double)ew[e] / d;
    }
}

// exclusive scan of g_cnt into g_rowoff (single block, chunked)
__global__ void k_scan() {
    __shared__ int sh[1024];
    __shared__ int carry;
    int t = threadIdx.x;
    if (t == 0) carry = 0;
    __syncthreads();
    for (int base = 0; base < NN; base += 1024) {
        int v = (base + t < NN) ? g_cnt[base + t] : 0;
        sh[t] = v;
        __syncthreads();
        for (int s = 1; s < 1024; s <<= 1) {
            int add = (t >= s) ? sh[t - s] : 0;
            __syncthreads();
            sh[t] += add;
            __syncthreads();
        }
        if (base + t < NN) g_rowoff[base + t + 1] = carry + sh[t];
        __syncthreads();
        if (t == 0) carry += sh[1023];
        __syncthreads();
    }
    if (t == 0) g_rowoff[0] = 0;
}

__global__ void k_scatter(const int* ei) {
    int e = blockIdx.x * blockDim.x + threadIdx.x;
    if (e < NE) {
        int r = ei[e];
        int pos = g_rowoff[r] + atomicAdd(&g_cur[r], 1);
        g_csrc[pos] = ei[NE + e];
        g_csrw[pos] = g_normwd[e];
    }
}

// embedding gather + per-channel sum/sumsq (fp64)
__global__ void k_embed(const int* x, const float* tab) {
    int c = threadIdx.x & 63;
    int rbase = blockIdx.x * 4 + (threadIdx.x >> 6);
    double s = 0.0, s2 = 0.0;
    for (int r = rbase; r < NN; r += gridDim.x * 4) {
        double v = (double)tab[x[r] * 64 + c];
        g_Ed[r * 64 + c] = v;
        s += v; s2 += v * v;
    }
    atomicAdd(&g_d[D_EMB + c], s);
    atomicAdd(&g_d[D_EMB + 64 + c], s2);
}

// per-channel sum/sumsq over a column slice of fp64 matrix
__global__ void k_gnsum(const double* x, int ld, int C, double* sums) {
    int c = threadIdx.x;   // blockDim.x == C
    double s = 0.0, s2 = 0.0;
    for (int r = blockIdx.x; r < NN; r += gridDim.x) {
        double v = x[r * ld + c];
        s += v; s2 += v * v;
    }
    atomicAdd(&sums[c], s);
    atomicAdd(&sums[C + c], s2);
}

// GraphNorm -> per-channel affine y = a*x + c  (all fp64)
__global__ void k_affine(const double* sums, const float* w, const float* b,
                         const float* ms, double* ac, int C, double invN) {
    int c = blockIdx.x * blockDim.x + threadIdx.x;
    if (c < C) {
        double mu = sums[c] * invN;
        double ex2 = sums[C + c] * invN;
        double m = (double)ms[c];
        double var = ex2 - 2.0 * m * mu * mu + m * m * mu * mu;
        double a = (double)w[c] / sqrt(var + EPSV);
        ac[c] = a;
        ac[C + c] = (double)b[c] - a * m * mu;
    }
}

// node Linear (fp64): out = relu( f(in)*W + b ), f = affine (+optional relu)
__global__ void k_lin(const double* in, int ldin, const double* ac, int prerelu,
                      const float* W, const float* bias) {
    __shared__ double Xs[32][65];
    __shared__ float  Ws[64][64];
    __shared__ double as_[64], cs_[64], bs_[64];
    int tid = threadIdx.x;
    for (int i = tid; i < 4096; i += 256) Ws[i >> 6][i & 63] = W[i];
    if (tid < 64) { as_[tid] = ac[tid]; cs_[tid] = ac[64 + tid]; bs_[tid] = (double)bias[tid]; }
    __syncthreads();
    int r0 = blockIdx.x * 32;
    for (int i = tid; i < 2048; i += 256) {
        int r = i >> 6, c = i & 63;
        int gr = r0 + r;
        double v = 0.0;
        if (gr < NN) {
            v = as_[c] * in[gr * ldin + c] + cs_[c];
            if (prerelu) v = fmax(v, 0.0);
        }
        Xs[r][c] = v;
    }
    __syncthreads();
    int c = (tid & 15) * 4, rr = (tid >> 4) * 2;
    double acc[2][4] = {};
    for (int k = 0; k < 64; k++) {
        double w0 = (double)Ws[k][c + 0];
        double w1 = (double)Ws[k][c + 1];
        double w2 = (double)Ws[k][c + 2];
        double w3 = (double)Ws[k][c + 3];
        #pragma unroll
        for (int i = 0; i < 2; i++) {
            double xv = Xs[rr + i][k];
            acc[i][0] += xv * w0; acc[i][1] += xv * w1;
            acc[i][2] += xv * w2; acc[i][3] += xv * w3;
        }
    }
    for (int i = 0; i < 2; i++) {
        int gr = r0 + rr + i;
        if (gr < NN) {
            #pragma unroll
            for (int j = 0; j < 4; j++)
                g_hlind[gr * 64 + c + j] = fmax(acc[i][j] + bs_[c + j], 0.0);
        }
    }
}

// CSR gather-SpMM (fp64, no atomics): one warp per row, 2 channels per lane
__global__ void k_spmm_csr(int coloff) {
    int w = (blockIdx.x * blockDim.x + threadIdx.x) >> 5;
    int lane = threadIdx.x & 31;
    if (w >= NN) return;
    int j0 = g_rowoff[w], j1 = g_rowoff[w + 1];
    double a0 = 0.0, a1 = 0.0;
    for (int j = j0; j < j1; j++) {
        int c = g_csrc[j];
        double wt = g_csrw[j];
        const double* src = &g_hlind[c * 64 + lane * 2];
        a0 += wt * src[0];
        a1 += wt * src[1];
    }
    double* dst = &g_hcatd[w * 192 + coloff + lane * 2];
    dst[0] = a0; dst[1] = a1;
}

// materialize normalized concat: hcatn = a_f*hcat + c_f
__global__ void k_normcat() {
    int r = blockIdx.x, f = threadIdx.x;   // <<<NN, 192>>>
    int idx = r * 192 + f;
    g_hcatnd[idx] = g_ac_gld[f] * g_hcatd[idx] + g_ac_gld[192 + f];
}

// s = hcatn @ sW + sb (fp64), softmax; fused: colsum, ss, mincut_den
__global__ void k_soft(const float* sW, const float* sb) {
    __shared__ double H[16][193];
    __shared__ float  Ws[3072];
    __shared__ double Sm[16][17];
    __shared__ float  sbs[16];
    int t = threadIdx.x;
    for (int i = t; i < 3072; i += 256) Ws[i] = sW[i];
    if (t < 16) sbs[t] = sb[t];
    int i_ = t >> 4, k_ = t & 15;
    double ss_acc = 0.0, col_acc = 0.0, den_acc = 0.0;
    for (int tile = blockIdx.x; tile < 3125; tile += gridDim.x) {
        int n0 = tile * 16;
        __syncthreads();
        for (int i = t; i < 16 * 192; i += 256) {
            int r = i / 192, f = i - r * 192;
            H[r][f] = g_hcatnd[(n0 + r) * 192 + f];
        }
        __syncthreads();
        {
            double acc = 0.0;
            for (int f = 0; f < 192; f++) acc += H[i_][f] * (double)Ws[f * 16 + k_];
            Sm[i_][k_] = acc + (double)sbs[k_];
        }
        __syncthreads();
        if (t < 16) {
            int gr = n0 + t;
            double mx = -1e300;
            #pragma unroll
            for (int j = 0; j < 16; j++) mx = fmax(mx, Sm[t][j]);
            double ev[16]; double s = 0.0;
            #pragma unroll
            for (int j = 0; j < 16; j++) { ev[j] = exp(Sm[t][j] - mx); s += ev[j]; }
            double inv = 1.0 / s;
            double sq = 0.0;
            #pragma unroll
            for (int j = 0; j < 16; j++) {
                double v = ev[j] * inv;
                Sm[t][j] = v;
                g_ssmd[gr * 16 + j] = v;
                g_ssmf[gr * 16 + j] = (float)v;
                sq += v * v;
            }
            den_acc += g_degd[gr] * sq;
        }
        __syncthreads();
        {
            double s = 0.0;
            #pragma unroll
            for (int i = 0; i < 16; i++) s += Sm[i][i_] * Sm[i][k_];
            ss_acc += s;
        }
        if (t < 16) {
            double s = 0.0;
            #pragma unroll
            for (int i = 0; i < 16; i++) s += Sm[i][t];
            col_acc += s;
        }
    }
    atomicAdd(&g_d[D_SS + t], ss_acc);
    if (t < 16) atomicAdd(&g_d[D_COLSUM + t], col_acc);
    if (t < 16) atomicAdd(&g_d[D_DEN], den_acc);
}

// mincut numerator: sum_e w[e] * <s_sm[row], s_sm[col]>  (fp64)
__global__ void k_num(const int* ei, const float* ew) {
    double acc = 0.0;
    for (int e = blockIdx.x * blockDim.x + threadIdx.x; e < NE;
         e += gridDim.x * blockDim.x) {
        int r = ei[e], c = ei[NE + e];
        const double* a = &g_ssmd[r * 16];
        const double* b = &g_ssmd[c * 16];
        double d = 0.0;
        #pragma unroll
        for (int i = 0; i < 16; i++) d += a[i] * b[i];
        acc += (double)ew[e] * d;
    }
    __shared__ double red[256];
    red[threadIdx.x] = acc; __syncthreads();
    for (int s = 128; s > 0; s >>= 1) {
        if (threadIdx.x < s) red[threadIdx.x] += red[threadIdx.x + s];
        __syncthreads();
    }
    if (threadIdx.x == 0) atomicAdd(&g_d[D_NUM], red[0]);
}

// out[k,f] = sum_n s_sm[n,k]*hcatn[n,f]  (fp64, persistent n-split)
__global__ void k_poolout() {
    __shared__ double Hs[8][193];
    __shared__ double Ss[8][16];
    int t = threadIdx.x;
    int k = t & 15, fb = (t >> 4) * 12;
    double acc[12];
    #pragma unroll
    for (int j = 0; j < 12; j++) acc[j] = 0.0;
    for (int tile = blockIdx.x; tile < 6250; tile += gridDim.x) {
        int r0 = tile * 8;
        __syncthreads();
        for (int i = t; i < 8 * 192; i += 256) {
            int r = i / 192, f = i - r * 192;
            Hs[r][f] = g_hcatnd[(r0 + r) * 192 + f];
        }
        if (t < 128) Ss[t >> 4][t & 15] = g_ssmd[(r0 + (t >> 4)) * 16 + (t & 15)];
        __syncthreads();
        #pragma unroll
        for (int i = 0; i < 8; i++) {
            double sv = Ss[i][k];
            #pragma unroll
            for (int j = 0; j < 12; j++) acc[j] += sv * Hs[i][fb + j];
        }
    }
    for (int j = 0; j < 12; j++)
        atomicAdd(&g_d[D_OUT + k * 192 + fb + j], acc[j]);
}

// ======= sort keys: fp32, 16-lane interleaved accumulation (winning scheme) =======
__global__ void k_sub2f32(const float* SA) {
    __shared__ float lred[16][17];
    int m = blockIdx.x;          // 256 blocks, one per subgraph
    int t = threadIdx.x;         // 256 threads: k = t>>4, lane = t&15
    int k = t >> 4, lane = t & 15;
    float cs = (float)g_d[D_COLSUM + k];
    if (cs < 1e-12f) cs = 1e-12f;
    float acc = 0.f;
    const float* sa = SA + (size_t)m * NN;
    for (int n = lane; n < NN; n += 16) {
        float sv = g_ssmf[n * 16 + k];
        float tv = sv / cs;
        acc = fmaf(tv, sa[n], acc);
    }
    lred[k][lane] = acc;
    __syncthreads();
    for (int s = 8; s > 0; s >>= 1) {
        if (lane < s) lred[k][lane] += lred[k][lane + s];
        __syncthreads();
    }
    if (lane == 0) g_sub2f[k * 256 + m] = lred[k][0];
}

// losses (fp64)
__global__ void k_fin(float* dout) {
    int t = threadIdx.x;
    __shared__ double red[256];
    __shared__ double fro;
    double v = g_d[D_SS + t];
    red[t] = v * v; __syncthreads();
    for (int s = 128; s > 0; s >>= 1) { if (t < s) red[t] += red[t + s]; __syncthreads(); }
    if (t == 0) fro = sqrt(red[0]);
    __syncthreads();
    double d = v / fro - (((t >> 4) == (t & 15)) ? 0.25 : 0.0);
    red[t] = d * d; __syncthreads();
    for (int s = 128; s > 0; s >>= 1) { if (t < s) red[t] += red[t + s]; __syncthreads(); }
    if (t == 0) {
        dout[16385] = (float)sqrt(red[0]);
        dout[16384] = (float)(-(g_d[D_NUM] / g_d[D_DEN]));
    }
}

// per-subgraph: stable sort clusters by fp32 score desc, emit emb row
__global__ void k_embbuild() {
    __shared__ float rs[16];
    __shared__ int perm[16];
    int m = blockIdx.x, t = threadIdx.x;
    if (t < 16) rs[t] = g_sub2f[t * 256 + m];
    __syncthreads();
    if (t == 0) {
        int p[16];
        for (int i = 0; i < 16; i++) p[i] = i;
        for (int i = 1; i < 16; i++) {
            int key = p[i]; float kv = rs[key];
            int j = i - 1;
            while (j >= 0 && rs[p[j]] < kv) { p[j + 1] = p[j]; j--; }
            p[j + 1] = key;
        }
        for (int i = 0; i < 16; i++) perm[i] = p[i];
    }
    __syncthreads();
    for (int idx = t; idx < 3088; idx += 256) {
        int j = idx / 193, f = idx - j * 193;
        int pk = perm[j];
        g_embd[m * 3088 + idx] = (f < 192) ? g_d[D_OUT + pk * 192 + f] : (double)rs[pk];
    }
}

// MLP layer 1: 256x3088 @ 3088x128 (fp64), split-K=16 with fp64 atomics
__global__ void k_mlp1(const float* W1) {
    int b = blockIdx.x;
    int rt = b & 7; b >>= 3; int ct = b & 1; int ks = b >> 1;
    int r0 = rt * 32, c0 = ct * 64, k0 = ks * 193;
    __shared__ double As[32][33];
    __shared__ float  Bs[32][64];
    int t = threadIdx.x;
    int c = (t & 15) * 4, rr = (t >> 4) * 2;
    double acc[2][4] = {};
    for (int kk = 0; kk < 193; kk += 32) {
        int kc = 193 - kk; if (kc > 32) kc = 32;
        for (int i = t; i < 32 * 32; i += 256) {
            int r = i >> 5, kx = i & 31;
            As[r][kx] = (kx < kc) ? g_embd[(r0 + r) * 3088 + k0 + kk + kx] : 0.0;
        }
        for (int i = t; i < 32 * 64; i += 256) {
            int kx = i >> 6, cc = i & 63;
            Bs[kx][cc] = (kx < kc) ? W1[(k0 + kk + kx) * 128 + c0 + cc] : 0.f;
        }
        __syncthreads();
        #pragma unroll 8
        for (int kx = 0; kx < 32; kx++) {
            double b0 = (double)Bs[kx][c + 0], b1 = (double)Bs[kx][c + 1];
            double b2 = (double)Bs[kx][c + 2], b3 = (double)Bs[kx][c + 3];
            double a0 = As[rr][kx], a1 = As[rr + 1][kx];
            acc[0][0] += a0 * b0; acc[0][1] += a0 * b1;
            acc[0][2] += a0 * b2; acc[0][3] += a0 * b3;
            acc[1][0] += a1 * b0; acc[1][1] += a1 * b1;
            acc[1][2] += a1 * b2; acc[1][3] += a1 * b3;
        }
        __syncthreads();
    }
    for (int i = 0; i < 2; i++)
        for (int j = 0; j < 4; j++)
            atomicAdd(&g_h1pred[(r0 + rr + i) * 128 + c0 + c + j], acc[i][j]);
}

__global__ void k_biasrelu(const float* b1) {
    int idx = blockIdx.x * blockDim.x + threadIdx.x;
    if (idx < 256 * 128)
        g_h1d[idx] = fmax(g_h1pred[idx] + (double)b1[idx & 127], 0.0);
}

// small dense layers fp64: 256x128 @ 128xCo
__global__ void k_mlps(const double* in, const float* W, const float* bias,
                       double* outd, float* outf, int Co, int dorelu) {
    __shared__ double As[32][129];
    int r0 = blockIdx.x * 32, c0 = blockIdx.y * 32;
    int t = threadIdx.x;
    for (int i = t; i < 32 * 128; i += 256) {
        int r = i >> 7, kx = i & 127;
        As[r][kx] = in[(r0 + r) * 128 + kx];
    }
    __syncthreads();
    int r = t >> 3, c = (t & 7) * 4;
    double a0 = 0, a1 = 0, a2 = 0, a3 = 0;
    for (int kx = 0; kx < 128; kx++) {
        double a = As[r][kx];
        const float* wrow = &W[kx * Co + c0 + c];
        a0 += a * (double)wrow[0]; a1 += a * (double)wrow[1];
        a2 += a * (double)wrow[2]; a3 += a * (double)wrow[3];
    }
    double o0 = a0 + (double)bias[c0 + c + 0];
    double o1 = a1 + (double)bias[c0 + c + 1];
    double o2 = a2 + (double)bias[c0 + c + 2];
    double o3 = a3 + (double)bias[c0 + c + 3];
    if (dorelu) { o0 = fmax(o0, 0.0); o1 = fmax(o1, 0.0); o2 = fmax(o2, 0.0); o3 = fmax(o3, 0.0); }
    int base = (r0 + r) * Co + c0 + c;
    if (outd) {
        outd[base + 0] = o0; outd[base + 1] = o1;
        outd[base + 2] = o2; outd[base + 3] = o3;
    } else {
        outf[base + 0] = (float)o0; outf[base + 1] = (float)o1;
        outf[base + 2] = (float)o2; outf[base + 3] = (float)o3;
    }
}

// ---------------- launch ----------------
extern "C" void kernel_launch(void* const* d_in, const int* in_sizes, int n_in,
                              void* d_out, int out_size) {
    const int*   x    = (const int*)d_in[0];
    const int*   ei   = (const int*)d_in[1];
    const float* ew   = (const float*)d_in[2];
    const float* SA   = (const float*)d_in[4];
    const float* tab  = (const float*)d_in[5];
    const float* egw  = (const float*)d_in[6];
    const float* egb  = (const float*)d_in[7];
    const float* egm  = (const float*)d_in[8];
    const float* cW   = (const float*)d_in[9];
    const float* cB   = (const float*)d_in[10];
    const float* gnw  = (const float*)d_in[11];
    const float* gnb  = (const float*)d_in[12];
    const float* gnm  = (const float*)d_in[13];
    const float* glw  = (const float*)d_in[14];
    const float* glb  = (const float*)d_in[15];
    const float* glm  = (const float*)d_in[16];
    const float* sW   = (const float*)d_in[17];
    const float* sb   = (const float*)d_in[18];
    const float* pW1  = (const float*)d_in[19];
    const float* pb1  = (const float*)d_in[20];
    const float* pW2  = (const float*)d_in[21];
    const float* pb2  = (const float*)d_in[22];
    const float* pW3  = (const float*)d_in[23];
    const float* pb3  = (const float*)d_in[24];
    const float* pW4  = (const float*)d_in[25];
    const float* pb4  = (const float*)d_in[26];
    float* out = (float*)d_out;

    void *pv;
    double *degd_p, *hcatd_p, *Ed_p, *aced, *ac0d, *ac1d, *acld;
    double *h1d_p, *h2d_p, *h3d_p, *h1pred_p, *d_p;
    int *cnt_p, *cur_p;
    cudaGetSymbolAddress(&pv, g_degd);    degd_p  = (double*)pv;
    cudaGetSymbolAddress(&pv, g_hcatd);   hcatd_p = (double*)pv;
    cudaGetSymbolAddress(&pv, g_Ed);      Ed_p    = (double*)pv;
    cudaGetSymbolAddress(&pv, g_ac_embd); aced    = (double*)pv;
    cudaGetSymbolAddress(&pv, g_ac_g0d);  ac0d    = (double*)pv;
    cudaGetSymbolAddress(&pv, g_ac_g1d);  ac1d    = (double*)pv;
    cudaGetSymbolAddress(&pv, g_ac_gld);  acld    = (double*)pv;
    cudaGetSymbolAddress(&pv, g_h1d);     h1d_p   = (double*)pv;
    cudaGetSymbolAddress(&pv, g_h2d);     h2d_p   = (double*)pv;
    cudaGetSymbolAddress(&pv, g_h3d);     h3d_p   = (double*)pv;
    cudaGetSymbolAddress(&pv, g_h1pred);  h1pred_p = (double*)pv;
    cudaGetSymbolAddress(&pv, g_d);       d_p     = (double*)pv;
    cudaGetSymbolAddress(&pv, g_cnt);     cnt_p   = (int*)pv;
    cudaGetSymbolAddress(&pv, g_cur);     cur_p   = (int*)pv;

    cudaMemsetAsync(degd_p, 0, (size_t)NN * 8);
    cudaMemsetAsync(h1pred_p, 0, (size_t)256 * 128 * 8);
    cudaMemsetAsync(d_p, 0, (size_t)D_TOTAL * 8);
    cudaMemsetAsync(cnt_p, 0, (size_t)NN * 4);
    cudaMemsetAsync(cur_p, 0, (size_t)NN * 4);

    const double invN = 1.0 / (double)NN;

    k_deg<<<3125, 256>>>(ei, ew);
    k_norm<<<3125, 256>>>(ei, ew);
    k_scan<<<1, 1024>>>();
    k_scatter<<<3125, 256>>>(ei);
    k_embed<<<256, 256>>>(x, tab);
    k_affine<<<1, 256>>>(d_p + D_EMB, egw, egb, egm, aced, 64, invN);

    // layer 0
    k_lin<<<1563, 256>>>(Ed_p, 64, aced, 0, cW, cB);
    k_spmm_csr<<<6250, 256>>>(0);
    k_gnsum<<<256, 64>>>(hcatd_p, 192, 64, d_p + D_G0);
    k_affine<<<1, 256>>>(d_p + D_G0, gnw, gnb, gnm, ac0d, 64, invN);
    // layer 1
    k_lin<<<1563, 256>>>(hcatd_p, 192, ac0d, 1, cW + 4096, cB + 64);
    k_spmm_csr<<<6250, 256>>>(64);
    k_gnsum<<<256, 64>>>(hcatd_p + 64, 192, 64, d_p + D_G1);
    k_affine<<<1, 256>>>(d_p + D_G1, gnw + 64, gnb + 64, gnm + 64, ac1d, 64, invN);
    // layer 2
    k_lin<<<1563, 256>>>(hcatd_p + 64, 192, ac1d, 1, cW + 8192, cB + 128);
    k_spmm_csr<<<6250, 256>>>(128);

    // final GraphNorm over concat -> materialized hcatn (fp64)
    k_gnsum<<<256, 192>>>(hcatd_p, 192, 192, d_p + D_GL);
    k_affine<<<1, 256>>>(d_p + D_GL, glw, glb, glm, acld, 192, invN);
    k_normcat<<<NN, 192>>>();

    k_soft<<<256, 256>>>(sW, sb);
    k_num<<<2048, 256>>>(ei, ew);
    k_poolout<<<256, 256>>>();
    k_sub2f32<<<256, 256>>>(SA);
    k_fin<<<1, 256>>>(out);
    k_embbuild<<<256, 256>>>();

    k_mlp1<<<256, 256>>>(pW1);
    k_biasrelu<<<128, 256>>>(pb1);
    k_mlps<<<dim3(8, 4), 256>>>(h1d_p, pW2, pb2, h2d_p, (float*)0, 128, 1);
    k_mlps<<<dim3(8, 4), 256>>>(h2d_p, pW3, pb3, h3d_p, (float*)0, 128, 1);
    k_mlps<<<dim3(8, 2), 256>>>(h3d_p, pW4, pb4, (double*)0, out, 64, 0);

    (void)in_sizes; (void)n_in; (void)out_size;
}

// round 9
// speedup vs baseline: 3.1264x; 2.9990x over previous
#include <cuda_runtime.h>
#include <math.h>

#define NN 50000
#define NE 800000
#define EPSV 1e-5

// ---------------- scratch (__device__ globals; no runtime alloc) ----------------
__device__ double g_degd[NN];          // fp64 degree (deterministic to 1e-16)
__device__ float  g_degf[NN];          // fp32 snapshot for mincut_den
__device__ float  g_normw[NE];
__device__ float  g_E[NN * 64];
__device__ float  g_hlin[NN * 64];
__device__ float  g_hcat[NN * 192];
__device__ float  g_hcatn[NN * 192];
__device__ float  g_ssmf[NN * 16];     // fp32 ssm (feeds key kernel — layout frozen)
__device__ double g_ac_embd[128];
__device__ double g_ac_g0d[128];
__device__ double g_ac_g1d[128];
__device__ double g_ac_gld[384];
__device__ float  g_outf[16 * 192];
__device__ float  g_emb[256 * 3088];
__device__ float  g_h1[256 * 128];
__device__ float  g_h2[256 * 128];
__device__ float  g_h3[256 * 128];
__device__ float  g_h1pre[256 * 128];
__device__ float  g_sub2f[16 * 256];   // fp32 sort keys (winning scheme — DO NOT TOUCH)

// CSR structures (built once per launch; rows canonically sorted -> deterministic)
__device__ int    g_cnt[NN];
__device__ int    g_cur[NN];
__device__ int    g_rowoff[NN + 1];
__device__ int    g_csrc[NE];
__device__ float  g_csrw[NE];

// fp64 accumulator zone (memset to 0 once per launch)
#define D_EMB    0      // 128
#define D_G0     128    // 128
#define D_G1     256    // 128
#define D_GL     384    // 384
#define D_COLSUM 768    // 16
#define D_SS     784    // 256
#define D_NUM    1040   // 1
#define D_DEN    1041   // 1
#define D_OUT    1048   // 3072
#define D_TOTAL  4120
__device__ double g_d[D_TOTAL];

// ---------------- kernels ----------------

__global__ void k_deg(const int* ei, const float* ew) {
    int e = blockIdx.x * blockDim.x + threadIdx.x;
    if (e < NE) {
        atomicAdd(&g_degd[ei[e]], (double)ew[e]);   // fp64: order jitter ~1e-16
        atomicAdd(&g_cnt[ei[e]], 1);
    }
}

__global__ void k_norm(const int* ei, const float* ew) {
    int e = blockIdx.x * blockDim.x + threadIdx.x;
    if (e < NE) {
        double d = g_degd[ei[e]];
        if (d < 0.5) d += 1.0;
        g_normw[e] = (float)((double)ew[e] / d);
    }
    if (e < NN) g_degf[e] = (float)g_degd[e];
}

// exclusive scan of g_cnt into g_rowoff (single block, chunked)
__global__ void k_scan() {
    __shared__ int sh[1024];
    __shared__ int carry;
    int t = threadIdx.x;
    if (t == 0) carry = 0;
    __syncthreads();
    for (int base = 0; base < NN; base += 1024) {
        int v = (base + t < NN) ? g_cnt[base + t] : 0;
        sh[t] = v;
        __syncthreads();
        for (int s = 1; s < 1024; s <<= 1) {
            int add = (t >= s) ? sh[t - s] : 0;
            __syncthreads();
            sh[t] += add;
            __syncthreads();
        }
        if (base + t < NN) g_rowoff[base + t + 1] = carry + sh[t];
        __syncthreads();
        if (t == 0) carry += sh[1023];
        __syncthreads();
    }
    if (t == 0) g_rowoff[0] = 0;
}

__global__ void k_scatter(const int* ei) {
    int e = blockIdx.x * blockDim.x + threadIdx.x;
    if (e < NE) {
        int r = ei[e];
        int pos = g_rowoff[r] + atomicAdd(&g_cur[r], 1);
        g_csrc[pos] = ei[NE + e];
        g_csrw[pos] = g_normw[e];
    }
}

// canonicalize each CSR row: insertion sort by (col, weight-bits).
// Row content becomes a deterministic function of the edge multiset,
// independent of atomic arrival order -> fp32 SpMM is deterministic.
__global__ void k_rowsort() {
    int r = blockIdx.x * blockDim.x + threadIdx.x;
    if (r >= NN) return;
    int j0 = g_rowoff[r], j1 = g_rowoff[r + 1];
    for (int i = j0 + 1; i < j1; i++) {
        int c = g_csrc[i];
        unsigned wb = __float_as_uint(g_csrw[i]);
        int j = i - 1;
        while (j >= j0) {
            int cj = g_csrc[j];
            unsigned wbj = __float_as_uint(g_csrw[j]);
            if (cj > c || (cj == c && wbj > wb)) {
                g_csrc[j + 1] = cj;
                g_csrw[j + 1] = __uint_as_float(wbj);
                j--;
            } else break;
        }
        g_csrc[j + 1] = c;
        g_csrw[j + 1] = __uint_as_float(wb);
    }
}

// embedding gather (fp32) + per-channel sum/sumsq (fp64 accumulate)
__global__ void k_embed(const int* x, const float* tab) {
    int c = threadIdx.x & 63;
    int rbase = blockIdx.x * 4 + (threadIdx.x >> 6);
    double s = 0.0, s2 = 0.0;
    for (int r = rbase; r < NN; r += gridDim.x * 4) {
        float v = tab[x[r] * 64 + c];
        g_E[r * 64 + c] = v;
        double vd = (double)v;
        s += vd; s2 += vd * vd;
    }
    atomicAdd(&g_d[D_EMB + c], s);
    atomicAdd(&g_d[D_EMB + 64 + c], s2);
}

// per-channel sum/sumsq over a column slice of fp32 matrix (fp64 accumulate)
__global__ void k_gnsum(const float* x, int ld, int C, double* sums) {
    int c = threadIdx.x;   // blockDim.x == C
    double s = 0.0, s2 = 0.0;
    for (int r = blockIdx.x; r < NN; r += gridDim.x) {
        double v = (double)x[r * ld + c];
        s += v; s2 += v * v;
    }
    atomicAdd(&sums[c], s);
    atomicAdd(&sums[C + c], s2);
}

// GraphNorm -> per-channel affine y = a*x + c  (fp64)
__global__ void k_affine(const double* sums, const float* w, const float* b,
                         const float* ms, double* ac, int C, double invN) {
    int c = blockIdx.x * blockDim.x + threadIdx.x;
    if (c < C) {
        double mu = sums[c] * invN;
        double ex2 = sums[C + c] * invN;
        double m = (double)ms[c];
        double var = ex2 - 2.0 * m * mu * mu + m * m * mu * mu;
        double a = (double)w[c] / sqrt(var + EPSV);
        ac[c] = a;
        ac[C + c] = (double)b[c] - a * m * mu;
    }
}

// node Linear fp32: out = relu( f(in)*W + b ), f = affine (+optional relu) on load
__global__ void k_lin(const float* in, int ldin, const double* ac, int prerelu,
                      const float* W, const float* bias) {
    __shared__ float Xs[64][65];
    __shared__ float Ws[64][64];
    __shared__ float as_[64], cs_[64], bs_[64];
    int tid = threadIdx.x;
    for (int i = tid; i < 4096; i += 256) Ws[i >> 6][i & 63] = W[i];
    if (tid < 64) {
        as_[tid] = (float)ac[tid];
        cs_[tid] = (float)ac[64 + tid];
        bs_[tid] = bias[tid];
    }
    __syncthreads();
    int r0 = blockIdx.x * 64;
    for (int i = tid; i < 4096; i += 256) {
        int r = i >> 6, c = i & 63;
        int gr = r0 + r;
        float v = 0.f;
        if (gr < NN) {
            v = fmaf(as_[c], in[gr * ldin + c], cs_[c]);
            if (prerelu) v = fmaxf(v, 0.f);
        }
        Xs[r][c] = v;
    }
    __syncthreads();
    int c = (tid & 15) * 4, rr = tid >> 4;
    float acc[4][4] = {};
    for (int k = 0; k < 64; k++) {
        float4 wv = *(const float4*)&Ws[k][c];
        #pragma unroll
        for (int i = 0; i < 4; i++) {
            float xv = Xs[rr + 16 * i][k];
            acc[i][0] = fmaf(xv, wv.x, acc[i][0]);
            acc[i][1] = fmaf(xv, wv.y, acc[i][1]);
            acc[i][2] = fmaf(xv, wv.z, acc[i][2]);
            acc[i][3] = fmaf(xv, wv.w, acc[i][3]);
        }
    }
    for (int i = 0; i < 4; i++) {
        int gr = r0 + rr + 16 * i;
        if (gr < NN) {
            float4 o;
            o.x = fmaxf(acc[i][0] + bs_[c + 0], 0.f);
            o.y = fmaxf(acc[i][1] + bs_[c + 1], 0.f);
            o.z = fmaxf(acc[i][2] + bs_[c + 2], 0.f);
            o.w = fmaxf(acc[i][3] + bs_[c + 3], 0.f);
            *(float4*)&g_hlin[gr * 64 + c] = o;
        }
    }
}

// CSR gather-SpMM fp32 (deterministic: rows canonically sorted)
__global__ void k_spmm_csr(int coloff) {
    int w = (blockIdx.x * blockDim.x + threadIdx.x) >> 5;
    int lane = threadIdx.x & 31;
    if (w >= NN) return;
    int j0 = g_rowoff[w], j1 = g_rowoff[w + 1];
    float a0 = 0.f, a1 = 0.f;
    for (int j = j0; j < j1; j++) {
        int c = g_csrc[j];
        float wt = g_csrw[j];
        float2 v = *(const float2*)&g_hlin[c * 64 + lane * 2];
        a0 = fmaf(wt, v.x, a0);
        a1 = fmaf(wt, v.y, a1);
    }
    float2 o = { a0, a1 };
    *(float2*)&g_hcat[w * 192 + coloff + lane * 2] = o;
}

// materialize normalized concat: hcatn = a_f*hcat + c_f (fp32 apply)
__global__ void k_normcat() {
    int r = blockIdx.x, f = threadIdx.x;   // <<<NN, 192>>>
    int idx = r * 192 + f;
    g_hcatn[idx] = fmaf((float)g_ac_gld[f], g_hcat[idx], (float)g_ac_gld[192 + f]);
}

// s = hcatn @ sW + sb (fp32), softmax fp32; fused fp64 partials: colsum, ss, den
__global__ void k_soft(const float* sW, const float* sb) {
    __shared__ float H[32][193];
    __shared__ float Ws[3072];
    __shared__ float Sm[32][17];
    __shared__ float sbs[16];
    int t = threadIdx.x;
    for (int i = t; i < 3072; i += 256) Ws[i] = sW[i];
    if (t < 16) sbs[t] = sb[t];
    int a_ = t >> 4, b_ = t & 15;
    double ss_acc = 0.0, col_acc = 0.0, den_acc = 0.0;
    for (int tile = blockIdx.x; tile < 1563; tile += gridDim.x) {
        int n0 = tile * 32;
        __syncthreads();
        for (int i = t; i < 32 * 192; i += 256) {
            int r = i / 192, f = i - r * 192;
            int gr = n0 + r;
            H[r][f] = (gr < NN) ? g_hcatn[gr * 192 + f] : 0.f;
        }
        __syncthreads();
        #pragma unroll
        for (int p = 0; p < 2; p++) {
            int i = a_ + 16 * p;
            float acc = 0.f;
            for (int f = 0; f < 192; f++) acc = fmaf(H[i][f], Ws[f * 16 + b_], acc);
            Sm[i][b_] = acc + sbs[b_];
        }
        __syncthreads();
        if (t < 32) {
            int gr = n0 + t;
            if (gr < NN) {
                float mx = -1e30f;
                #pragma unroll
                for (int j = 0; j < 16; j++) mx = fmaxf(mx, Sm[t][j]);
                float ev[16]; float s = 0.f;
                #pragma unroll
                for (int j = 0; j < 16; j++) { ev[j] = expf(Sm[t][j] - mx); s += ev[j]; }
                float inv = 1.f / s;
                float sq = 0.f;
                #pragma unroll
                for (int j = 0; j < 16; j++) {
                    float v = ev[j] * inv;
                    Sm[t][j] = v;
                    g_ssmf[gr * 16 + j] = v;
                    sq += v * v;
                }
                den_acc += (double)(g_degf[gr] * sq);
            } else {
                #pragma unroll
                for (int j = 0; j < 16; j++) Sm[t][j] = 0.f;
            }
        }
        __syncthreads();
        {
            float s = 0.f;
            #pragma unroll
            for (int i = 0; i < 32; i++) s += Sm[i][a_] * Sm[i][b_];
            ss_acc += (double)s;
        }
        if (t < 16) {
            float s = 0.f;
            #pragma unroll
            for (int i = 0; i < 32; i++) s += Sm[i][t];
            col_acc += (double)s;
        }
    }
    atomicAdd(&g_d[D_SS + t], ss_acc);
    if (t < 16) atomicAdd(&g_d[D_COLSUM + t], col_acc);
    if (t < 32) atomicAdd(&g_d[D_DEN], den_acc);
}

// mincut numerator: sum_e w[e] * <ssm[row], ssm[col]>  (fp32 dot, fp64 reduce)
__global__ void k_num(const int* ei, const float* ew) {
    float acc = 0.f;
    for (int e = blockIdx.x * blockDim.x + threadIdx.x; e < NE;
         e += gridDim.x * blockDim.x) {
        int r = ei[e], c = ei[NE + e];
        const float4* a = (const float4*)&g_ssmf[r * 16];
        const float4* b = (const float4*)&g_ssmf[c * 16];
        float d = 0.f;
        #pragma unroll
        for (int i = 0; i < 4; i++) {
            float4 av = a[i], bv = b[i];
            d += av.x * bv.x + av.y * bv.y + av.z * bv.z + av.w * bv.w;
        }
        acc = fmaf(ew[e], d, acc);
    }
    __shared__ double red[256];
    red[threadIdx.x] = (double)acc; __syncthreads();
    for (int s = 128; s > 0; s >>= 1) {
        if (threadIdx.x < s) red[threadIdx.x] += red[threadIdx.x + s];
        __syncthreads();
    }
    if (threadIdx.x == 0) atomicAdd(&g_d[D_NUM], red[0]);
}

// out[k,f] = sum_n ssm[n,k]*hcatn[n,f]  (fp32 tiles, fp64 atomic finish)
__global__ void k_poolout() {
    __shared__ float Hs[8][193];
    __shared__ float Ss[8][16];
    int t = threadIdx.x;
    int k = t & 15, fb = (t >> 4) * 12;
    float acc[12];
    #pragma unroll
    for (int j = 0; j < 12; j++) acc[j] = 0.f;
    for (int tile = blockIdx.x; tile < 6250; tile += gridDim.x) {
        int r0 = tile * 8;
        __syncthreads();
        for (int i = t; i < 8 * 192; i += 256) {
            int r = i / 192, f = i - r * 192;
            Hs[r][f] = g_hcatn[(r0 + r) * 192 + f];
        }
        if (t < 128) Ss[t >> 4][t & 15] = g_ssmf[(r0 + (t >> 4)) * 16 + (t & 15)];
        __syncthreads();
        #pragma unroll
        for (int i = 0; i < 8; i++) {
            float sv = Ss[i][k];
            #pragma unroll
            for (int j = 0; j < 12; j++) acc[j] = fmaf(sv, Hs[i][fb + j], acc[j]);
        }
    }
    for (int j = 0; j < 12; j++)
        atomicAdd(&g_d[D_OUT + k * 192 + fb + j], (double)acc[j]);
}

// ======= sort keys: fp32, 16-lane interleaved accumulation (winning scheme) =======
__global__ void k_sub2f32(const float* SA) {
    __shared__ float lred[16][17];
    int m = blockIdx.x;          // 256 blocks, one per subgraph
    int t = threadIdx.x;         // 256 threads: k = t>>4, lane = t&15
    int k = t >> 4, lane = t & 15;
    float cs = (float)g_d[D_COLSUM + k];
    if (cs < 1e-12f) cs = 1e-12f;
    float acc = 0.f;
    const float* sa = SA + (size_t)m * NN;
    for (int n = lane; n < NN; n += 16) {
        float sv = g_ssmf[n * 16 + k];
        float tv = sv / cs;
        acc = fmaf(tv, sa[n], acc);
    }
    lred[k][lane] = acc;
    __syncthreads();
    for (int s = 8; s > 0; s >>= 1) {
        if (lane < s) lred[k][lane] += lred[k][lane + s];
        __syncthreads();
    }
    if (lane == 0) g_sub2f[k * 256 + m] = lred[k][0];
}

// losses (fp64) + out conversion
__global__ void k_fin(float* dout) {
    int t = threadIdx.x;
    __shared__ double red[256];
    __shared__ double fro;
    for (int idx = t; idx < 3072; idx += 256)
        g_outf[idx] = (float)g_d[D_OUT + idx];
    double v = g_d[D_SS + t];
    red[t] = v * v; __syncthreads();
    for (int s = 128; s > 0; s >>= 1) { if (t < s) red[t] += red[t + s]; __syncthreads(); }
    if (t == 0) fro = sqrt(red[0]);
    __syncthreads();
    double d = v / fro - (((t >> 4) == (t & 15)) ? 0.25 : 0.0);
    red[t] = d * d; __syncthreads();
    for (int s = 128; s > 0; s >>= 1) { if (t < s) red[t] += red[t + s]; __syncthreads(); }
    if (t == 0) {
        dout[16385] = (float)sqrt(red[0]);
        dout[16384] = (float)(-(g_d[D_NUM] / g_d[D_DEN]));
    }
}

// per-subgraph: stable sort clusters by fp32 score desc, emit emb row (fp32)
__global__ void k_embbuild() {
    __shared__ float rs[16];
    __shared__ int perm[16];
    int m = blockIdx.x, t = threadIdx.x;
    if (t < 16) rs[t] = g_sub2f[t * 256 + m];
    __syncthreads();
    if (t == 0) {
        int p[16];
        for (int i = 0; i < 16; i++) p[i] = i;
        for (int i = 1; i < 16; i++) {
            int key = p[i]; float kv = rs[key];
            int j = i - 1;
            while (j >= 0 && rs[p[j]] < kv) { p[j + 1] = p[j]; j--; }
            p[j + 1] = key;
        }
        for (int i = 0; i < 16; i++) perm[i] = p[i];
    }
    __syncthreads();
    for (int idx = t; idx < 3088; idx += 256) {
        int j = idx / 193, f = idx - j * 193;
        int pk = perm[j];
        g_emb[m * 3088 + idx] = (f < 192) ? g_outf[pk * 192 + f] : rs[pk];
    }
}

// MLP layer 1: 256x3088 @ 3088x128 fp32, split-K=16 with fp32 atomic accumulate
__global__ void k_mlp1(const float* W1) {
    int b = blockIdx.x;
    int rt = b & 7; b >>= 3; int ct = b & 1; int ks = b >> 1;
    int r0 = rt * 32, c0 = ct * 64, k0 = ks * 193;
    __shared__ float As[32][33];
    __shared__ float Bs[32][64];
    int t = threadIdx.x;
    int c = (t & 15) * 4, rr = (t >> 4) * 2;
    float acc[2][4] = {};
    for (int kk = 0; kk < 193; kk += 32) {
        int kc = 193 - kk; if (kc > 32) kc = 32;
        for (int i = t; i < 32 * 32; i += 256) {
            int r = i >> 5, kx = i & 31;
            As[r][kx] = (kx < kc) ? g_emb[(r0 + r) * 3088 + k0 + kk + kx] : 0.f;
        }
        for (int i = t; i < 32 * 64; i += 256) {
            int kx = i >> 6, cc = i & 63;
            Bs[kx][cc] = (kx < kc) ? W1[(k0 + kk + kx) * 128 + c0 + cc] : 0.f;
        }
        __syncthreads();
        #pragma unroll 8
        for (int kx = 0; kx < 32; kx++) {
            float4 bv = *(const float4*)&Bs[kx][c];
            float a0 = As[rr][kx], a1 = As[rr + 1][kx];
            acc[0][0] = fmaf(a0, bv.x, acc[0][0]); acc[0][1] = fmaf(a0, bv.y, acc[0][1]);
            acc[0][2] = fmaf(a0, bv.z, acc[0][2]); acc[0][3] = fmaf(a0, bv.w, acc[0][3]);
            acc[1][0] = fmaf(a1, bv.x, acc[1][0]); acc[1][1] = fmaf(a1, bv.y, acc[1][1]);
            acc[1][2] = fmaf(a1, bv.z, acc[1][2]); acc[1][3] = fmaf(a1, bv.w, acc[1][3]);
        }
        __syncthreads();
    }
    for (int i = 0; i < 2; i++)
        for (int j = 0; j < 4; j++)
            atomicAdd(&g_h1pre[(r0 + rr + i) * 128 + c0 + c + j], acc[i][j]);
}

__global__ void k_biasrelu(const float* b1) {
    int idx = blockIdx.x * blockDim.x + threadIdx.x;
    if (idx < 256 * 128)
        g_h1[idx] = fmaxf(g_h1pre[idx] + b1[idx & 127], 0.f);
}

// small dense layers fp32: 256x128 @ 128xCo
__global__ void k_mlps(const float* in, const float* W, const float* bias,
                       float* out, int Co, int dorelu) {
    __shared__ float As[32][129];
    __shared__ float Bs[128 * 32];
    int r0 = blockIdx.x * 32, c0 = blockIdx.y * 32;
    int t = threadIdx.x;
    for (int i = t; i < 32 * 128; i += 256) {
        int r = i >> 7, kx = i & 127;
        As[r][kx] = in[(r0 + r) * 128 + kx];
    }
    for (int i = t; i < 128 * 32; i += 256) {
        int kx = i >> 5, cc = i & 31;
        Bs[kx * 32 + cc] = W[kx * Co + c0 + cc];
    }
    __syncthreads();
    int r = t >> 3, c = (t & 7) * 4;
    float4 acc = { 0.f, 0.f, 0.f, 0.f };
    #pragma unroll 8
    for (int kx = 0; kx < 128; kx++) {
        float a = As[r][kx];
        float4 bv = *(const float4*)&Bs[kx * 32 + c];
        acc.x = fmaf(a, bv.x, acc.x); acc.y = fmaf(a, bv.y, acc.y);
        acc.z = fmaf(a, bv.z, acc.z); acc.w = fmaf(a, bv.w, acc.w);
    }
    float o0 = acc.x + bias[c0 + c + 0];
    float o1 = acc.y + bias[c0 + c + 1];
    float o2 = acc.z + bias[c0 + c + 2];
    float o3 = acc.w + bias[c0 + c + 3];
    if (dorelu) { o0 = fmaxf(o0, 0.f); o1 = fmaxf(o1, 0.f); o2 = fmaxf(o2, 0.f); o3 = fmaxf(o3, 0.f); }
    out[(r0 + r) * Co + c0 + c + 0] = o0;
    out[(r0 + r) * Co + c0 + c + 1] = o1;
    out[(r0 + r) * Co + c0 + c + 2] = o2;
    out[(r0 + r) * Co + c0 + c + 3] = o3;
}

// ---------------- launch ----------------
extern "C" void kernel_launch(void* const* d_in, const int* in_sizes, int n_in,
                              void* d_out, int out_size) {
    const int*   x    = (const int*)d_in[0];
    const int*   ei   = (const int*)d_in[1];
    const float* ew   = (const float*)d_in[2];
    const float* SA   = (const float*)d_in[4];
    const float* tab  = (const float*)d_in[5];
    const float* egw  = (const float*)d_in[6];
    const float* egb  = (const float*)d_in[7];
    const float* egm  = (const float*)d_in[8];
    const float* cW   = (const float*)d_in[9];
    const float* cB   = (const float*)d_in[10];
    const float* gnw  = (const float*)d_in[11];
    const float* gnb  = (const float*)d_in[12];
    const float* gnm  = (const float*)d_in[13];
    const float* glw  = (const float*)d_in[14];
    const float* glb  = (const float*)d_in[15];
    const float* glm  = (const float*)d_in[16];
    const float* sW   = (const float*)d_in[17];
    const float* sb   = (const float*)d_in[18];
    const float* pW1  = (const float*)d_in[19];
    const float* pb1  = (const float*)d_in[20];
    const float* pW2  = (const float*)d_in[21];
    const float* pb2  = (const float*)d_in[22];
    const float* pW3  = (const float*)d_in[23];
    const float* pb3  = (const float*)d_in[24];
    const float* pW4  = (const float*)d_in[25];
    const float* pb4  = (const float*)d_in[26];
    float* out = (float*)d_out;

    void *pv;
    float *E_p, *hcat_p, *h1p, *h2p, *h3p, *h1pre_p;
    double *degd_p, *aced, *ac0d, *ac1d, *acld, *d_p;
    int *cnt_p, *cur_p;
    cudaGetSymbolAddress(&pv, g_degd);    degd_p  = (double*)pv;
    cudaGetSymbolAddress(&pv, g_E);       E_p     = (float*)pv;
    cudaGetSymbolAddress(&pv, g_hcat);    hcat_p  = (float*)pv;
    cudaGetSymbolAddress(&pv, g_ac_embd); aced    = (double*)pv;
    cudaGetSymbolAddress(&pv, g_ac_g0d);  ac0d    = (double*)pv;
    cudaGetSymbolAddress(&pv, g_ac_g1d);  ac1d    = (double*)pv;
    cudaGetSymbolAddress(&pv, g_ac_gld);  acld    = (double*)pv;
    cudaGetSymbolAddress(&pv, g_h1);      h1p     = (float*)pv;
    cudaGetSymbolAddress(&pv, g_h2);      h2p     = (float*)pv;
    cudaGetSymbolAddress(&pv, g_h3);      h3p     = (float*)pv;
    cudaGetSymbolAddress(&pv, g_h1pre);   h1pre_p = (float*)pv;
    cudaGetSymbolAddress(&pv, g_d);       d_p     = (double*)pv;
    cudaGetSymbolAddress(&pv, g_cnt);     cnt_p   = (int*)pv;
    cudaGetSymbolAddress(&pv, g_cur);     cur_p   = (int*)pv;

    cudaMemsetAsync(degd_p, 0, (size_t)NN * 8);
    cudaMemsetAsync(h1pre_p, 0, (size_t)256 * 128 * 4);
    cudaMemsetAsync(d_p, 0, (size_t)D_TOTAL * 8);
    cudaMemsetAsync(cnt_p, 0, (size_t)NN * 4);
    cudaMemsetAsync(cur_p, 0, (size_t)NN * 4);

    const double invN = 1.0 / (double)NN;

    k_deg<<<3125, 256>>>(ei, ew);
    k_norm<<<3125, 256>>>(ei, ew);
    k_scan<<<1, 1024>>>();
    k_scatter<<<3125, 256>>>(ei);
    k_rowsort<<<196, 256>>>();
    k_embed<<<256, 256>>>(x, tab);
    k_affine<<<1, 256>>>(d_p + D_EMB, egw, egb, egm, aced, 64, invN);

    // layer 0
    k_lin<<<782, 256>>>(E_p, 64, aced, 0, cW, cB);
    k_spmm_csr<<<6250, 256>>>(0);
    k_gnsum<<<256, 64>>>(hcat_p, 192, 64, d_p + D_G0);
    k_affine<<<1, 256>>>(d_p + D_G0, gnw, gnb, gnm, ac0d, 64, invN);
    // layer 1
    k_lin<<<782, 256>>>(hcat_p, 192, ac0d, 1, cW + 4096, cB + 64);
    k_spmm_csr<<<6250, 256>>>(64);
    k_gnsum<<<256, 64>>>(hcat_p + 64, 192, 64, d_p + D_G1);
    k_affine<<<1, 256>>>(d_p + D_G1, gnw + 64, gnb + 64, gnm + 64, ac1d, 64, invN);
    // layer 2
    k_lin<<<782, 256>>>(hcat_p + 64, 192, ac1d, 1, cW + 8192, cB + 128);
    k_spmm_csr<<<6250, 256>>>(128);

    // final GraphNorm over concat -> materialized hcatn (fp32, fp64 stats)
    k_gnsum<<<256, 192>>>(hcat_p, 192, 192, d_p + D_GL);
    k_affine<<<1, 256>>>(d_p + D_GL, glw, glb, glm, acld, 192, invN);
    k_normcat<<<NN, 192>>>();

    k_soft<<<256, 256>>>(sW, sb);
    k_num<<<2048, 256>>>(ei, ew);
    k_poolout<<<256, 256>>>();
    k_sub2f32<<<256, 256>>>(SA);
    k_fin<<<1, 256>>>(out);
    k_embbuild<<<256, 256>>>();

    k_mlp1<<<256, 256>>>(pW1);
    k_biasrelu<<<128, 256>>>(pb1);
    k_mlps<<<dim3(8, 4), 256>>>(h1p, pW2, pb2, h2p, 128, 1);
    k_mlps<<<dim3(8, 4), 256>>>(h2p, pW3, pb3, h3p, 128, 1);
    k_mlps<<<dim3(8, 2), 256>>>(h3p, pW4, pb4, out, 64, 0);

    (void)in_sizes; (void)n_in; (void)out_size;
}

// round 10
// speedup vs baseline: 5.2921x; 1.6927x over previous
#include <cuda_runtime.h>
#include <math.h>

#define NN 50000
#define NE 800000
#define EPSV 1e-5

// ---------------- scratch (__device__ globals; no runtime alloc) ----------------
__device__ double g_degd[NN];          // fp64 degree (deterministic to 1e-16)
__device__ float  g_degf[NN];          // fp32 snapshot for mincut_den
__device__ float  g_normw[NE];
__device__ float  g_E[NN * 64];
__device__ float  g_hlin[NN * 64];
__device__ float  g_hcat[NN * 192];
__device__ float  g_ssmf[NN * 16];     // fp32 ssm (feeds key kernel — layout frozen)
__device__ float  g_outf[16 * 192];
__device__ float  g_emb[256 * 3088];
__device__ float  g_h1[256 * 128];
__device__ float  g_h2[256 * 128];
__device__ float  g_h3[256 * 128];
__device__ float  g_h1pre[256 * 128];
__device__ float  g_sub2f[16 * 256];   // fp32 sort keys (winning realization — FROZEN)

// CSR structures (built once per launch; rows canonically sorted -> deterministic)
__device__ int    g_cnt[NN];
__device__ int    g_cur[NN];
__device__ int    g_rowoff[NN + 1];
__device__ int2   g_csre[NE];          // (col, weight-bits)
__device__ int    g_rowtmp[50176];
__device__ int    g_bsum[64];

// fp64 accumulator zone (memset to 0 once per launch)
#define D_EMB    0      // 128
#define D_G0     128    // 128
#define D_G1     256    // 128
#define D_GL     384    // 384
#define D_COLSUM 768    // 16
#define D_SS     784    // 256
#define D_NUM    1040   // 1
#define D_DEN    1041   // 1
#define D_OUT    1048   // 3072
#define D_TOTAL  4120
__device__ double g_d[D_TOTAL];

// GraphNorm affine from fp64 stats (identical math to old k_affine)
__device__ __forceinline__ void affine_pair(const double* sums, const float* w,
        const float* b, const float* ms, int C, double invN, int c,
        float* a_out, float* c_out) {
    double mu = sums[c] * invN;
    double ex2 = sums[C + c] * invN;
    double m = (double)ms[c];
    double var = ex2 - 2.0 * m * mu * mu + m * m * mu * mu;
    double a = (double)w[c] / sqrt(var + EPSV);
    *a_out = (float)a;
    *c_out = (float)((double)b[c] - a * m * mu);
}

// ---------------- kernels ----------------

__global__ void k_deg(const int* ei, const float* ew) {
    int e = blockIdx.x * blockDim.x + threadIdx.x;
    if (e < NE) {
        atomicAdd(&g_degd[ei[e]], (double)ew[e]);
        atomicAdd(&g_cnt[ei[e]], 1);
    }
}

__global__ void k_norm(const int* ei, const float* ew) {
    int e = blockIdx.x * blockDim.x + threadIdx.x;
    if (e < NE) {
        double d = g_degd[ei[e]];
        if (d < 0.5) d += 1.0;
        g_normw[e] = (float)((double)ew[e] / d);
    }
    if (e < NN) g_degf[e] = (float)g_degd[e];
}

// 3-phase deterministic int scan
__global__ void k_scan1() {
    __shared__ int sh[1024];
    int t = threadIdx.x, b = blockIdx.x;
    int idx = b * 1024 + t;
    int v = (idx < NN) ? g_cnt[idx] : 0;
    sh[t] = v; __syncthreads();
    for (int s = 1; s < 1024; s <<= 1) {
        int add = (t >= s) ? sh[t - s] : 0;
        __syncthreads();
        sh[t] += add;
        __syncthreads();
    }
    g_rowtmp[idx] = sh[t];
    if (t == 1023) g_bsum[b] = sh[t];
}
__global__ void k_scan2() {
    if (threadIdx.x == 0) {
        int acc = 0;
        for (int i = 0; i < 49; i++) { int v = g_bsum[i]; g_bsum[i] = acc; acc += v; }
    }
}
__global__ void k_scan3() {
    int t = threadIdx.x, b = blockIdx.x;
    int idx = b * 1024 + t;
    if (idx < NN) g_rowoff[idx + 1] = g_rowtmp[idx] + g_bsum[b];
    if (idx == 0) g_rowoff[0] = 0;
}

__global__ void k_scatter(const int* ei) {
    int e = blockIdx.x * blockDim.x + threadIdx.x;
    if (e < NE) {
        int r = ei[e];
        int pos = g_rowoff[r] + atomicAdd(&g_cur[r], 1);
        g_csre[pos] = make_int2(ei[NE + e], __float_as_int(g_normw[e]));
    }
}

// canonicalize each CSR row: insertion sort by (col, weight-bits) — frozen order
__global__ void k_rowsort() {
    int r = blockIdx.x * blockDim.x + threadIdx.x;
    if (r >= NN) return;
    int j0 = g_rowoff[r], j1 = g_rowoff[r + 1];
    for (int i = j0 + 1; i < j1; i++) {
        int2 e = g_csre[i];
        int j = i - 1;
        while (j >= j0) {
            int2 ej = g_csre[j];
            if (ej.x > e.x || (ej.x == e.x && (unsigned)ej.y > (unsigned)e.y)) {
                g_csre[j + 1] = ej; j--;
            } else break;
        }
        g_csre[j + 1] = e;
    }
}

// embedding gather (fp32) + per-channel sum/sumsq (fp64 accumulate)
__global__ void k_embed(const int* x, const float* tab) {
    int c = threadIdx.x & 63;
    int rbase = blockIdx.x * 4 + (threadIdx.x >> 6);
    double s = 0.0, s2 = 0.0;
    for (int r = rbase; r < NN; r += gridDim.x * 4) {
        float v = tab[x[r] * 64 + c];
        g_E[r * 64 + c] = v;
        double vd = (double)v;
        s += vd; s2 += vd * vd;
    }
    atomicAdd(&g_d[D_EMB + c], s);
    atomicAdd(&g_d[D_EMB + 64 + c], s2);
}

// per-channel sum/sumsq over a column slice of fp32 matrix (fp64 accumulate)
__global__ void k_gnsum(const float* x, int ld, int C, double* sums) {
    int c = threadIdx.x;   // blockDim.x == C
    double s = 0.0, s2 = 0.0;
    for (int r = blockIdx.x; r < NN; r += gridDim.x) {
        double v = (double)x[r * ld + c];
        s += v; s2 += v * v;
    }
    atomicAdd(&sums[c], s);
    atomicAdd(&sums[C + c], s2);
}

// node Linear fp32 with inlined GN affine: out = relu( f(in)*W + b )
__global__ void k_lin(const float* in, int ldin, const double* sums,
                      const float* gw, const float* gb, const float* gm,
                      int prerelu, const float* W, const float* bias, double invN) {
    __shared__ float Xs[64][65];
    __shared__ float Ws[64][64];
    __shared__ float as_[64], cs_[64], bs_[64];
    int tid = threadIdx.x;
    for (int i = tid; i < 4096; i += 256) Ws[i >> 6][i & 63] = W[i];
    if (tid < 64) {
        affine_pair(sums, gw, gb, gm, 64, invN, tid, &as_[tid], &cs_[tid]);
        bs_[tid] = bias[tid];
    }
    __syncthreads();
    int r0 = blockIdx.x * 64;
    for (int i = tid; i < 4096; i += 256) {
        int r = i >> 6, c = i & 63;
        int gr = r0 + r;
        float v = 0.f;
        if (gr < NN) {
            v = fmaf(as_[c], in[gr * ldin + c], cs_[c]);
            if (prerelu) v = fmaxf(v, 0.f);
        }
        Xs[r][c] = v;
    }
    __syncthreads();
    int c = (tid & 15) * 4, rr = tid >> 4;
    float acc[4][4] = {};
    for (int k = 0; k < 64; k++) {
        float4 wv = *(const float4*)&Ws[k][c];
        #pragma unroll
        for (int i = 0; i < 4; i++) {
            float xv = Xs[rr + 16 * i][k];
            acc[i][0] = fmaf(xv, wv.x, acc[i][0]);
            acc[i][1] = fmaf(xv, wv.y, acc[i][1]);
            acc[i][2] = fmaf(xv, wv.z, acc[i][2]);
            acc[i][3] = fmaf(xv, wv.w, acc[i][3]);
        }
    }
    for (int i = 0; i < 4; i++) {
        int gr = r0 + rr + 16 * i;
        if (gr < NN) {
            float4 o;
            o.x = fmaxf(acc[i][0] + bs_[c + 0], 0.f);
            o.y = fmaxf(acc[i][1] + bs_[c + 1], 0.f);
            o.z = fmaxf(acc[i][2] + bs_[c + 2], 0.f);
            o.w = fmaxf(acc[i][3] + bs_[c + 3], 0.f);
            *(float4*)&g_hlin[gr * 64 + c] = o;
        }
    }
}

// CSR gather-SpMM fp32 (deterministic: rows canonically sorted)
__global__ void k_spmm_csr(int coloff) {
    int w = (blockIdx.x * blockDim.x + threadIdx.x) >> 5;
    int lane = threadIdx.x & 31;
    if (w >= NN) return;
    int j0 = g_rowoff[w], j1 = g_rowoff[w + 1];
    float a0 = 0.f, a1 = 0.f;
    for (int j = j0; j < j1; j++) {
        int2 e = g_csre[j];
        float wt = __int_as_float(e.y);
        float2 v = *(const float2*)&g_hlin[e.x * 64 + lane * 2];
        a0 = fmaf(wt, v.x, a0);
        a1 = fmaf(wt, v.y, a1);
    }
    float2 o = { a0, a1 };
    *(float2*)&g_hcat[w * 192 + coloff + lane * 2] = o;
}

// s = gn(hcat) @ sW + sb (fp32, affine fused on load — bitwise == old normcat path),
// softmax fp32; fused fp64 partials: colsum, ss, den
__global__ void k_soft(const float* sW, const float* sb, const double* sums,
                       const float* glw, const float* glb, const float* glm,
                       double invN) {
    __shared__ float H[32][193];
    __shared__ float Ws[3072];
    __shared__ float Sm[32][17];
    __shared__ float sbs[16];
    __shared__ float af[192], cf[192];
    int t = threadIdx.x;
    for (int i = t; i < 3072; i += 256) Ws[i] = sW[i];
    if (t < 16) sbs[t] = sb[t];
    if (t < 192) affine_pair(sums, glw, glb, glm, 192, invN, t, &af[t], &cf[t]);
    int a_ = t >> 4, b_ = t & 15;
    double ss_acc = 0.0, col_acc = 0.0, den_acc = 0.0;
    for (int tile = blockIdx.x; tile < 1563; tile += gridDim.x) {
        int n0 = tile * 32;
        __syncthreads();
        for (int i = t; i < 32 * 192; i += 256) {
            int r = i / 192, f = i - r * 192;
            int gr = n0 + r;
            H[r][f] = (gr < NN) ? fmaf(af[f], g_hcat[gr * 192 + f], cf[f]) : 0.f;
        }
        __syncthreads();
        #pragma unroll
        for (int p = 0; p < 2; p++) {
            int i = a_ + 16 * p;
            float acc = 0.f;
            for (int f = 0; f < 192; f++) acc = fmaf(H[i][f], Ws[f * 16 + b_], acc);
            Sm[i][b_] = acc + sbs[b_];
        }
        __syncthreads();
        if (t < 32) {
            int gr = n0 + t;
            if (gr < NN) {
                float mx = -1e30f;
                #pragma unroll
                for (int j = 0; j < 16; j++) mx = fmaxf(mx, Sm[t][j]);
                float ev[16]; float s = 0.f;
                #pragma unroll
                for (int j = 0; j < 16; j++) { ev[j] = expf(Sm[t][j] - mx); s += ev[j]; }
                float inv = 1.f / s;
                float sq = 0.f;
                #pragma unroll
                for (int j = 0; j < 16; j++) {
                    float v = ev[j] * inv;
                    Sm[t][j] = v;
                    g_ssmf[gr * 16 + j] = v;
                    sq += v * v;
                }
                den_acc += (double)(g_degf[gr] * sq);
            } else {
                #pragma unroll
                for (int j = 0; j < 16; j++) Sm[t][j] = 0.f;
            }
        }
        __syncthreads();
        {
            float s = 0.f;
            #pragma unroll
            for (int i = 0; i < 32; i++) s += Sm[i][a_] * Sm[i][b_];
            ss_acc += (double)s;
        }
        if (t < 16) {
            float s = 0.f;
            #pragma unroll
            for (int i = 0; i < 32; i++) s += Sm[i][t];
            col_acc += (double)s;
        }
    }
    atomicAdd(&g_d[D_SS + t], ss_acc);
    if (t < 16) atomicAdd(&g_d[D_COLSUM + t], col_acc);
    if (t < 32) atomicAdd(&g_d[D_DEN], den_acc);
}

// mincut numerator: sum_e w[e] * <ssm[row], ssm[col]>  (fp32 dot, fp64 reduce)
__global__ void k_num(const int* ei, const float* ew) {
    float acc = 0.f;
    for (int e = blockIdx.x * blockDim.x + threadIdx.x; e < NE;
         e += gridDim.x * blockDim.x) {
        int r = ei[e], c = ei[NE + e];
        const float4* a = (const float4*)&g_ssmf[r * 16];
        const float4* b = (const float4*)&g_ssmf[c * 16];
        float d = 0.f;
        #pragma unroll
        for (int i = 0; i < 4; i++) {
            float4 av = a[i], bv = b[i];
            d += av.x * bv.x + av.y * bv.y + av.z * bv.z + av.w * bv.w;
        }
        acc = fmaf(ew[e], d, acc);
    }
    __shared__ double red[256];
    red[threadIdx.x] = (double)acc; __syncthreads();
    for (int s = 128; s > 0; s >>= 1) {
        if (threadIdx.x < s) red[threadIdx.x] += red[threadIdx.x + s];
        __syncthreads();
    }
    if (threadIdx.x == 0) atomicAdd(&g_d[D_NUM], red[0]);
}

// out[k,f] = sum_n ssm[n,k]*gn(hcat)[n,f]  (fp32 tiles, affine fused, fp64 finish)
__global__ void k_poolout(const double* sums, const float* glw, const float* glb,
                          const float* glm, double invN) {
    __shared__ float Hs[8][193];
    __shared__ float Ss[8][16];
    __shared__ float af[192], cf[192];
    int t = threadIdx.x;
    int k = t & 15, fb = (t >> 4) * 12;
    if (t < 192) affine_pair(sums, glw, glb, glm, 192, invN, t, &af[t], &cf[t]);
    float acc[12];
    #pragma unroll
    for (int j = 0; j < 12; j++) acc[j] = 0.f;
    for (int tile = blockIdx.x; tile < 6250; tile += gridDim.x) {
        int r0 = tile * 8;
        __syncthreads();
        for (int i = t; i < 8 * 192; i += 256) {
            int r = i / 192, f = i - r * 192;
            Hs[r][f] = fmaf(af[f], g_hcat[(r0 + r) * 192 + f], cf[f]);
        }
        if (t < 128) Ss[t >> 4][t & 15] = g_ssmf[(r0 + (t >> 4)) * 16 + (t & 15)];
        __syncthreads();
        #pragma unroll
        for (int i = 0; i < 8; i++) {
            float sv = Ss[i][k];
            #pragma unroll
            for (int j = 0; j < 12; j++) acc[j] = fmaf(sv, Hs[i][fb + j], acc[j]);
        }
    }
    for (int j = 0; j < 12; j++)
        atomicAdd(&g_d[D_OUT + k * 192 + fb + j], (double)acc[j]);
}

// ======= sort keys: fp32, 16-lane interleaved accumulation (FROZEN realization) ====
// v2: smem-staged, 2 subgraphs per block. Per-(k,m) fmaf sequence and the 16-lane
// pairwise tree are bitwise identical to the winning kernel; only memory path differs.
#define S2CH 512
__global__ void k_sub2v2(const float* SA) {
    __shared__ float sss[S2CH * 17];
    __shared__ float sa0[S2CH], sa1[S2CH];
    __shared__ float lr[2][16][17];
    int t = threadIdx.x;
    int k = t >> 4, lane = t & 15;
    int m0 = blockIdx.x, m1 = blockIdx.x + 128;
    float cs = (float)g_d[D_COLSUM + k];
    if (cs < 1e-12f) cs = 1e-12f;
    const float* sA0 = SA + (size_t)m0 * NN;
    const float* sA1 = SA + (size_t)m1 * NN;
    float acc0 = 0.f, acc1 = 0.f;
    for (int n0 = 0; n0 < NN; n0 += S2CH) {
        int span = NN - n0; if (span > S2CH) span = S2CH;
        __syncthreads();
        for (int i = t; i < span * 16; i += 256) {
            int n2 = i >> 4, kk = i & 15;
            sss[n2 * 17 + kk] = g_ssmf[(n0 + n2) * 16 + kk];
        }
        for (int i = t; i < span; i += 256) { sa0[i] = sA0[n0 + i]; sa1[i] = sA1[n0 + i]; }
        __syncthreads();
        for (int n2 = lane; n2 < span; n2 += 16) {
            float sv = sss[n2 * 17 + k];
            float tv = sv / cs;
            acc0 = fmaf(tv, sa0[n2], acc0);
            acc1 = fmaf(tv, sa1[n2], acc1);
        }
    }
    lr[0][k][lane] = acc0; lr[1][k][lane] = acc1;
    __syncthreads();
    for (int s = 8; s > 0; s >>= 1) {
        if (lane < s) {
            lr[0][k][lane] += lr[0][k][lane + s];
            lr[1][k][lane] += lr[1][k][lane + s];
        }
        __syncthreads();
    }
    if (lane == 0) {
        g_sub2f[k * 256 + m0] = lr[0][k][0];
        g_sub2f[k * 256 + m1] = lr[1][k][0];
    }
}

// losses (fp64) + out conversion
__global__ void k_fin(float* dout) {
    int t = threadIdx.x;
    __shared__ double red[256];
    __shared__ double fro;
    for (int idx = t; idx < 3072; idx += 256)
        g_outf[idx] = (float)g_d[D_OUT + idx];
    double v = g_d[D_SS + t];
    red[t] = v * v; __syncthreads();
    for (int s = 128; s > 0; s >>= 1) { if (t < s) red[t] += red[t + s]; __syncthreads(); }
    if (t == 0) fro = sqrt(red[0]);
    __syncthreads();
    double d = v / fro - (((t >> 4) == (t & 15)) ? 0.25 : 0.0);
    red[t] = d * d; __syncthreads();
    for (int s = 128; s > 0; s >>= 1) { if (t < s) red[t] += red[t + s]; __syncthreads(); }
    if (t == 0) {
        dout[16385] = (float)sqrt(red[0]);
        dout[16384] = (float)(-(g_d[D_NUM] / g_d[D_DEN]));
    }
}

// per-subgraph: stable sort clusters by fp32 score desc, emit emb row (fp32)
__global__ void k_embbuild() {
    __shared__ float rs[16];
    __shared__ int perm[16];
    int m = blockIdx.x, t = threadIdx.x;
    if (t < 16) rs[t] = g_sub2f[t * 256 + m];
    __syncthreads();
    if (t == 0) {
        int p[16];
        for (int i = 0; i < 16; i++) p[i] = i;
        for (int i = 1; i < 16; i++) {
            int key = p[i]; float kv = rs[key];
            int j = i - 1;
            while (j >= 0 && rs[p[j]] < kv) { p[j + 1] = p[j]; j--; }
            p[j + 1] = key;
        }
        for (int i = 0; i < 16; i++) perm[i] = p[i];
    }
    __syncthreads();
    for (int idx = t; idx < 3088; idx += 256) {
        int j = idx / 193, f = idx - j * 193;
        int pk = perm[j];
        g_emb[m * 3088 + idx] = (f < 192) ? g_outf[pk * 192 + f] : rs[pk];
    }
}

// MLP layer 1: 256x3088 @ 3088x128 fp32, split-K=16 with fp32 atomic accumulate
__global__ void k_mlp1(const float* W1) {
    int b = blockIdx.x;
    int rt = b & 7; b >>= 3; int ct = b & 1; int ks = b >> 1;
    int r0 = rt * 32, c0 = ct * 64, k0 = ks * 193;
    __shared__ float As[32][33];
    __shared__ float Bs[32][64];
    int t = threadIdx.x;
    int c = (t & 15) * 4, rr = (t >> 4) * 2;
    float acc[2][4] = {};
    for (int kk = 0; kk < 193; kk += 32) {
        int kc = 193 - kk; if (kc > 32) kc = 32;
        for (int i = t; i < 32 * 32; i += 256) {
            int r = i >> 5, kx = i & 31;
            As[r][kx] = (kx < kc) ? g_emb[(r0 + r) * 3088 + k0 + kk + kx] : 0.f;
        }
        for (int i = t; i < 32 * 64; i += 256) {
            int kx = i >> 6, cc = i & 63;
            Bs[kx][cc] = (kx < kc) ? W1[(k0 + kk + kx) * 128 + c0 + cc] : 0.f;
        }
        __syncthreads();
        #pragma unroll 8
        for (int kx = 0; kx < 32; kx++) {
            float4 bv = *(const float4*)&Bs[kx][c];
            float a0 = As[rr][kx], a1 = As[rr + 1][kx];
            acc[0][0] = fmaf(a0, bv.x, acc[0][0]); acc[0][1] = fmaf(a0, bv.y, acc[0][1]);
            acc[0][2] = fmaf(a0, bv.z, acc[0][2]); acc[0][3] = fmaf(a0, bv.w, acc[0][3]);
            acc[1][0] = fmaf(a1, bv.x, acc[1][0]); acc[1][1] = fmaf(a1, bv.y, acc[1][1]);
            acc[1][2] = fmaf(a1, bv.z, acc[1][2]); acc[1][3] = fmaf(a1, bv.w, acc[1][3]);
        }
        __syncthreads();
    }
    for (int i = 0; i < 2; i++)
        for (int j = 0; j < 4; j++)
            atomicAdd(&g_h1pre[(r0 + rr + i) * 128 + c0 + c + j], acc[i][j]);
}

__global__ void k_biasrelu(const float* b1) {
    int idx = blockIdx.x * blockDim.x + threadIdx.x;
    if (idx < 256 * 128)
        g_h1[idx] = fmaxf(g_h1pre[idx] + b1[idx & 127], 0.f);
}

// small dense layers fp32: 256x128 @ 128xCo
__global__ void k_mlps(const float* in, const float* W, const float* bias,
                       float* out, int Co, int dorelu) {
    __shared__ float As[32][129];
    __shared__ float Bs[128 * 32];
    int r0 = blockIdx.x * 32, c0 = blockIdx.y * 32;
    int t = threadIdx.x;
    for (int i = t; i < 32 * 128; i += 256) {
        int r = i >> 7, kx = i & 127;
        As[r][kx] = in[(r0 + r) * 128 + kx];
    }
    for (int i = t; i < 128 * 32; i += 256) {
        int kx = i >> 5, cc = i & 31;
        Bs[kx * 32 + cc] = W[kx * Co + c0 + cc];
    }
    __syncthreads();
    int r = t >> 3, c = (t & 7) * 4;
    float4 acc = { 0.f, 0.f, 0.f, 0.f };
    #pragma unroll 8
    for (int kx = 0; kx < 128; kx++) {
        float a = As[r][kx];
        float4 bv = *(const float4*)&Bs[kx * 32 + c];
        acc.x = fmaf(a, bv.x, acc.x); acc.y = fmaf(a, bv.y, acc.y);
        acc.z = fmaf(a, bv.z, acc.z); acc.w = fmaf(a, bv.w, acc.w);
    }
    float o0 = acc.x + bias[c0 + c + 0];
    float o1 = acc.y + bias[c0 + c + 1];
    float o2 = acc.z + bias[c0 + c + 2];
    float o3 = acc.w + bias[c0 + c + 3];
    if (dorelu) { o0 = fmaxf(o0, 0.f); o1 = fmaxf(o1, 0.f); o2 = fmaxf(o2, 0.f); o3 = fmaxf(o3, 0.f); }
    out[(r0 + r) * Co + c0 + c + 0] = o0;
    out[(r0 + r) * Co + c0 + c + 1] = o1;
    out[(r0 + r) * Co + c0 + c + 2] = o2;
    out[(r0 + r) * Co + c0 + c + 3] = o3;
}

// ---------------- launch ----------------
extern "C" void kernel_launch(void* const* d_in, const int* in_sizes, int n_in,
                              void* d_out, int out_size) {
    const int*   x    = (const int*)d_in[0];
    const int*   ei   = (const int*)d_in[1];
    const float* ew   = (const float*)d_in[2];
    const float* SA   = (const float*)d_in[4];
    const float* tab  = (const float*)d_in[5];
    const float* egw  = (const float*)d_in[6];
    const float* egb  = (const float*)d_in[7];
    const float* egm  = (const float*)d_in[8];
    const float* cW   = (const float*)d_in[9];
    const float* cB   = (const float*)d_in[10];
    const float* gnw  = (const float*)d_in[11];
    const float* gnb  = (const float*)d_in[12];
    const float* gnm  = (const float*)d_in[13];
    const float* glw  = (const float*)d_in[14];
    const float* glb  = (const float*)d_in[15];
    const float* glm  = (const float*)d_in[16];
    const float* sW   = (const float*)d_in[17];
    const float* sb   = (const float*)d_in[18];
    const float* pW1  = (const float*)d_in[19];
    const float* pb1  = (const float*)d_in[20];
    const float* pW2  = (const float*)d_in[21];
    const float* pb2  = (const float*)d_in[22];
    const float* pW3  = (const float*)d_in[23];
    const float* pb3  = (const float*)d_in[24];
    const float* pW4  = (const float*)d_in[25];
    const float* pb4  = (const float*)d_in[26];
    float* out = (float*)d_out;

    void *pv;
    float *E_p, *hcat_p, *h1p, *h2p, *h3p, *h1pre_p;
    double *degd_p, *d_p;
    int *cnt_p, *cur_p;
    cudaGetSymbolAddress(&pv, g_degd);    degd_p  = (double*)pv;
    cudaGetSymbolAddress(&pv, g_E);       E_p     = (float*)pv;
    cudaGetSymbolAddress(&pv, g_hcat);    hcat_p  = (float*)pv;
    cudaGetSymbolAddress(&pv, g_h1);      h1p     = (float*)pv;
    cudaGetSymbolAddress(&pv, g_h2);      h2p     = (float*)pv;
    cudaGetSymbolAddress(&pv, g_h3);      h3p     = (float*)pv;
    cudaGetSymbolAddress(&pv, g_h1pre);   h1pre_p = (float*)pv;
    cudaGetSymbolAddress(&pv, g_d);       d_p     = (double*)pv;
    cudaGetSymbolAddress(&pv, g_cnt);     cnt_p   = (int*)pv;
    cudaGetSymbolAddress(&pv, g_cur);     cur_p   = (int*)pv;

    cudaMemsetAsync(degd_p, 0, (size_t)NN * 8);
    cudaMemsetAsync(h1pre_p, 0, (size_t)256 * 128 * 4);
    cudaMemsetAsync(d_p, 0, (size_t)D_TOTAL * 8);
    cudaMemsetAsync(cnt_p, 0, (size_t)NN * 4);
    cudaMemsetAsync(cur_p, 0, (size_t)NN * 4);

    const double invN = 1.0 / (double)NN;

    k_deg<<<3125, 256>>>(ei, ew);
    k_norm<<<3125, 256>>>(ei, ew);
    k_scan1<<<49, 1024>>>();
    k_scan2<<<1, 64>>>();
    k_scan3<<<49, 1024>>>();
    k_scatter<<<3125, 256>>>(ei);
    k_rowsort<<<196, 256>>>();
    k_embed<<<256, 256>>>(x, tab);

    // layer 0
    k_lin<<<782, 256>>>(E_p, 64, d_p + D_EMB, egw, egb, egm, 0, cW, cB, invN);
    k_spmm_csr<<<6250, 256>>>(0);
    k_gnsum<<<256, 64>>>(hcat_p, 192, 64, d_p + D_G0);
    // layer 1
    k_lin<<<782, 256>>>(hcat_p, 192, d_p + D_G0, gnw, gnb, gnm, 1, cW + 4096, cB + 64, invN);
    k_spmm_csr<<<6250, 256>>>(64);
    k_gnsum<<<256, 64>>>(hcat_p + 64, 192, 64, d_p + D_G1);
    // layer 2
    k_lin<<<782, 256>>>(hcat_p + 64, 192, d_p + D_G1, gnw + 64, gnb + 64, gnm + 64,
                        1, cW + 8192, cB + 128, invN);
    k_spmm_csr<<<6250, 256>>>(128);

    // final GraphNorm stats over concat (affine applied inline downstream)
    k_gnsum<<<256, 192>>>(hcat_p, 192, 192, d_p + D_GL);

    k_soft<<<256, 256>>>(sW, sb, d_p + D_GL, glw, glb, glm, invN);
    k_num<<<2048, 256>>>(ei, ew);
    k_poolout<<<256, 256>>>(d_p + D_GL, glw, glb, glm, invN);
    k_sub2v2<<<128, 256>>>(SA);
    k_fin<<<1, 256>>>(out);
    k_embbuild<<<256, 256>>>();

    k_mlp1<<<256, 256>>>(pW1);
    k_biasrelu<<<128, 256>>>(pb1);
    k_mlps<<<dim3(8, 4), 256>>>(h1p, pW2, pb2, h2p, 128, 1);
    k_mlps<<<dim3(8, 4), 256>>>(h2p, pW3, pb3, h3p, 128, 1);
    k_mlps<<<dim3(8, 2), 256>>>(h3p, pW4, pb4, out, 64, 0);

    (void)in_sizes; (void)n_in; (void)out_size;
}

// round 11
// speedup vs baseline: 5.7852x; 1.0932x over previous
#include <cuda_runtime.h>
#include <math.h>

#define NN 50000
#define NE 800000
#define EPSV 1e-5

// ---------------- scratch (__device__ globals; no runtime alloc) ----------------
__device__ double g_degd[NN];          // fp64 degree (deterministic to 1e-16)
__device__ float  g_degf[NN];          // fp32 snapshot for mincut_den
__device__ float  g_normw[NE];
__device__ float  g_E[NN * 64];
__device__ float  g_hlin[NN * 64];
__device__ float  g_hcat[NN * 192];
__device__ float  g_ssmf[NN * 16];     // fp32 ssm (feeds key kernel — layout frozen)
__device__ float  g_outf[16 * 192];
__device__ float  g_emb[256 * 3088];
__device__ float  g_h1[256 * 128];
__device__ float  g_h2[256 * 128];
__device__ float  g_h3[256 * 128];
__device__ float  g_h1pre[256 * 128];
__device__ float  g_sub2f[16 * 256];   // fp32 sort keys (winning realization — FROZEN)

// CSR structures (built once per launch; rows canonically sorted -> deterministic)
__device__ int    g_cnt[NN];
__device__ int    g_cur[NN];
__device__ int    g_rowoff[NN + 1];
__device__ int2   g_csre[NE];          // (col, weight-bits)
__device__ int    g_rowtmp[50176];
__device__ int    g_bsum[64];

// fp64 accumulator zone (memset to 0 once per launch)
#define D_EMB    0      // 128
#define D_G0     128    // 128
#define D_G1     256    // 128
#define D_GL     384    // 384
#define D_COLSUM 768    // 16
#define D_SS     784    // 256
#define D_NUM    1040   // 1
#define D_DEN    1041   // 1
#define D_OUT    1048   // 3072
#define D_TOTAL  4120
__device__ double g_d[D_TOTAL];

// GraphNorm affine from fp64 stats (identical math across rounds)
__device__ __forceinline__ void affine_pair(const double* sums, const float* w,
        const float* b, const float* ms, int C, double invN, int c,
        float* a_out, float* c_out) {
    double mu = sums[c] * invN;
    double ex2 = sums[C + c] * invN;
    double m = (double)ms[c];
    double var = ex2 - 2.0 * m * mu * mu + m * m * mu * mu;
    double a = (double)w[c] / sqrt(var + EPSV);
    *a_out = (float)a;
    *c_out = (float)((double)b[c] - a * m * mu);
}

// ---------------- kernels ----------------

__global__ void k_deg(const int* ei, const float* ew) {
    int e = blockIdx.x * blockDim.x + threadIdx.x;
    if (e < NE) {
        atomicAdd(&g_degd[ei[e]], (double)ew[e]);
        atomicAdd(&g_cnt[ei[e]], 1);
    }
}

__global__ void k_norm(const int* ei, const float* ew) {
    int e = blockIdx.x * blockDim.x + threadIdx.x;
    if (e < NE) {
        double d = g_degd[ei[e]];
        if (d < 0.5) d += 1.0;
        g_normw[e] = (float)((double)ew[e] / d);
    }
    if (e < NN) g_degf[e] = (float)g_degd[e];
}

// 3-phase deterministic int scan
__global__ void k_scan1() {
    __shared__ int sh[1024];
    int t = threadIdx.x, b = blockIdx.x;
    int idx = b * 1024 + t;
    int v = (idx < NN) ? g_cnt[idx] : 0;
    sh[t] = v; __syncthreads();
    for (int s = 1; s < 1024; s <<= 1) {
        int add = (t >= s) ? sh[t - s] : 0;
        __syncthreads();
        sh[t] += add;
        __syncthreads();
    }
    g_rowtmp[idx] = sh[t];
    if (t == 1023) g_bsum[b] = sh[t];
}
__global__ void k_scan2() {
    if (threadIdx.x == 0) {
        int acc = 0;
        for (int i = 0; i < 49; i++) { int v = g_bsum[i]; g_bsum[i] = acc; acc += v; }
    }
}
__global__ void k_scan3() {
    int t = threadIdx.x, b = blockIdx.x;
    int idx = b * 1024 + t;
    if (idx < NN) g_rowoff[idx + 1] = g_rowtmp[idx] + g_bsum[b];
    if (idx == 0) g_rowoff[0] = 0;
}

__global__ void k_scatter(const int* ei) {
    int e = blockIdx.x * blockDim.x + threadIdx.x;
    if (e < NE) {
        int r = ei[e];
        int pos = g_rowoff[r] + atomicAdd(&g_cur[r], 1);
        g_csre[pos] = make_int2(ei[NE + e], __float_as_int(g_normw[e]));
    }
}

// canonicalize each CSR row: insertion sort by (col, weight-bits) — frozen order
__global__ void k_rowsort() {
    int r = blockIdx.x * blockDim.x + threadIdx.x;
    if (r >= NN) return;
    int j0 = g_rowoff[r], j1 = g_rowoff[r + 1];
    for (int i = j0 + 1; i < j1; i++) {
        int2 e = g_csre[i];
        int j = i - 1;
        while (j >= j0) {
            int2 ej = g_csre[j];
            if (ej.x > e.x || (ej.x == e.x && (unsigned)ej.y > (unsigned)e.y)) {
                g_csre[j + 1] = ej; j--;
            } else break;
        }
        g_csre[j + 1] = e;
    }
}

// embedding gather (fp32) + per-channel sum/sumsq (fp64 accumulate)
__global__ void k_embed(const int* x, const float* tab) {
    int c = threadIdx.x & 63;
    int rbase = blockIdx.x * 4 + (threadIdx.x >> 6);
    double s = 0.0, s2 = 0.0;
    for (int r = rbase; r < NN; r += gridDim.x * 4) {
        float v = tab[x[r] * 64 + c];
        g_E[r * 64 + c] = v;
        double vd = (double)v;
        s += vd; s2 += vd * vd;
    }
    atomicAdd(&g_d[D_EMB + c], s);
    atomicAdd(&g_d[D_EMB + 64 + c], s2);
}

// node Linear fp32 with inlined GN affine: out = relu( f(in)*W + b )
__global__ void k_lin(const float* in, int ldin, const double* sums,
                      const float* gw, const float* gb, const float* gm,
                      int prerelu, const float* W, const float* bias, double invN) {
    __shared__ float Xs[64][65];
    __shared__ float Ws[64][64];
    __shared__ float as_[64], cs_[64], bs_[64];
    int tid = threadIdx.x;
    for (int i = tid; i < 4096; i += 256) Ws[i >> 6][i & 63] = W[i];
    if (tid < 64) {
        affine_pair(sums, gw, gb, gm, 64, invN, tid, &as_[tid], &cs_[tid]);
        bs_[tid] = bias[tid];
    }
    __syncthreads();
    int r0 = blockIdx.x * 64;
    for (int i = tid; i < 4096; i += 256) {
        int r = i >> 6, c = i & 63;
        int gr = r0 + r;
        float v = 0.f;
        if (gr < NN) {
            v = fmaf(as_[c], in[gr * ldin + c], cs_[c]);
            if (prerelu) v = fmaxf(v, 0.f);
        }
        Xs[r][c] = v;
    }
    __syncthreads();
    int c = (tid & 15) * 4, rr = tid >> 4;
    float acc[4][4] = {};
    for (int k = 0; k < 64; k++) {
        float4 wv = *(const float4*)&Ws[k][c];
        #pragma unroll
        for (int i = 0; i < 4; i++) {
            float xv = Xs[rr + 16 * i][k];
            acc[i][0] = fmaf(xv, wv.x, acc[i][0]);
            acc[i][1] = fmaf(xv, wv.y, acc[i][1]);
            acc[i][2] = fmaf(xv, wv.z, acc[i][2]);
            acc[i][3] = fmaf(xv, wv.w, acc[i][3]);
        }
    }
    for (int i = 0; i < 4; i++) {
        int gr = r0 + rr + 16 * i;
        if (gr < NN) {
            float4 o;
            o.x = fmaxf(acc[i][0] + bs_[c + 0], 0.f);
            o.y = fmaxf(acc[i][1] + bs_[c + 1], 0.f);
            o.z = fmaxf(acc[i][2] + bs_[c + 2], 0.f);
            o.w = fmaxf(acc[i][3] + bs_[c + 3], 0.f);
            *(float4*)&g_hlin[gr * 64 + c] = o;
        }
    }
}

// CSR gather-SpMM fp32 (deterministic row order) + FUSED GN channel stats (fp64).
// Row compute is bitwise identical to round 10; stats replace the k_gnsum pass.
// sL: layer stats [64 sums][64 sumsq] or NULL; sG: concat stats base (D_GL).
__global__ void k_spmm_csr(int coloff, double* sL, double* sG) {
    __shared__ double sh[128];            // [0:64] sum, [64:128] sumsq
    int t = threadIdx.x, lane = t & 31, wid = t >> 5;
    if (t < 128) sh[t] = 0.0;
    __syncthreads();
    int w0 = blockIdx.x * 8 + wid;
    int stride = gridDim.x * 8;
    double s0 = 0.0, s1 = 0.0, q0 = 0.0, q1 = 0.0;
    for (int w = w0; w < NN; w += stride) {
        int j0 = g_rowoff[w], j1 = g_rowoff[w + 1];
        float a0 = 0.f, a1 = 0.f;
        for (int j = j0; j < j1; j++) {
            int2 e = g_csre[j];
            float wt = __int_as_float(e.y);
            float2 v = *(const float2*)&g_hlin[e.x * 64 + lane * 2];
            a0 = fmaf(wt, v.x, a0);
            a1 = fmaf(wt, v.y, a1);
        }
        float2 o = { a0, a1 };
        *(float2*)&g_hcat[w * 192 + coloff + lane * 2] = o;
        double d0 = (double)a0, d1 = (double)a1;
        s0 += d0; s1 += d1; q0 += d0 * d0; q1 += d1 * d1;
    }
    atomicAdd(&sh[lane * 2 + 0], s0);
    atomicAdd(&sh[lane * 2 + 1], s1);
    atomicAdd(&sh[64 + lane * 2 + 0], q0);
    atomicAdd(&sh[64 + lane * 2 + 1], q1);
    __syncthreads();
    if (t < 64) {
        double ssum = sh[t], sq = sh[64 + t];
        atomicAdd(&sG[coloff + t], ssum);
        atomicAdd(&sG[192 + coloff + t], sq);
        if (sL) {
            atomicAdd(&sL[t], ssum);
            atomicAdd(&sL[64 + t], sq);
        }
    }
}

// s = gn(hcat) @ sW + sb (fp32), softmax fp32 (FROZEN realization for g_ssmf);
// fused fp64 partials: colsum, ss, den; MERGED poolout: out[k,f] partials from
// the already-resident H (affined hcat) and Sm (ssm) tiles.
__global__ void k_soft(const float* sW, const float* sb, const double* sums,
                       const float* glw, const float* glb, const float* glm,
                       double invN) {
    __shared__ float H[32][193];
    __shared__ float Ws[3072];
    __shared__ float Sm[32][17];
    __shared__ float sbs[16];
    __shared__ float af[192], cf[192];
    int t = threadIdx.x;
    for (int i = t; i < 3072; i += 256) Ws[i] = sW[i];
    if (t < 16) sbs[t] = sb[t];
    if (t < 192) affine_pair(sums, glw, glb, glm, 192, invN, t, &af[t], &cf[t]);
    int a_ = t >> 4, b_ = t & 15;
    int kp = t & 15, fbp = (t >> 4) * 12;     // poolout mapping (as in old k_poolout)
    double ss_acc = 0.0, col_acc = 0.0, den_acc = 0.0;
    float po[12];
    #pragma unroll
    for (int j = 0; j < 12; j++) po[j] = 0.f;
    for (int tile = blockIdx.x; tile < 1563; tile += gridDim.x) {
        int n0 = tile * 32;
        __syncthreads();
        for (int i = t; i < 32 * 192; i += 256) {
            int r = i / 192, f = i - r * 192;
            int gr = n0 + r;
            H[r][f] = (gr < NN) ? fmaf(af[f], g_hcat[gr * 192 + f], cf[f]) : 0.f;
        }
        __syncthreads();
        #pragma unroll
        for (int p = 0; p < 2; p++) {
            int i = a_ + 16 * p;
            float acc = 0.f;
            for (int f = 0; f < 192; f++) acc = fmaf(H[i][f], Ws[f * 16 + b_], acc);
            Sm[i][b_] = acc + sbs[b_];
        }
        __syncthreads();
        if (t < 32) {
            int gr = n0 + t;
            if (gr < NN) {
                float mx = -1e30f;
                #pragma unroll
                for (int j = 0; j < 16; j++) mx = fmaxf(mx, Sm[t][j]);
                float ev[16]; float s = 0.f;
                #pragma unroll
                for (int j = 0; j < 16; j++) { ev[j] = expf(Sm[t][j] - mx); s += ev[j]; }
                float inv = 1.f / s;
                float sq = 0.f;
                #pragma unroll
                for (int j = 0; j < 16; j++) {
                    float v = ev[j] * inv;
                    Sm[t][j] = v;
                    g_ssmf[gr * 16 + j] = v;
                    sq += v * v;
                }
                den_acc += (double)(g_degf[gr] * sq);
            } else {
                #pragma unroll
                for (int j = 0; j < 16; j++) Sm[t][j] = 0.f;
            }
        }
        __syncthreads();
        {
            float s = 0.f;
            #pragma unroll
            for (int i = 0; i < 32; i++) s += Sm[i][a_] * Sm[i][b_];
            ss_acc += (double)s;
        }
        if (t < 16) {
            float s = 0.f;
            #pragma unroll
            for (int i = 0; i < 32; i++) s += Sm[i][t];
            col_acc += (double)s;
        }
        // merged poolout: out[kp, fbp..fbp+11] partials from this tile
        #pragma unroll 4
        for (int i = 0; i < 32; i++) {
            float sv = Sm[i][kp];
            #pragma unroll
            for (int j = 0; j < 12; j++) po[j] = fmaf(sv, H[i][fbp + j], po[j]);
        }
    }
    atomicAdd(&g_d[D_SS + t], ss_acc);
    if (t < 16) atomicAdd(&g_d[D_COLSUM + t], col_acc);
    if (t < 32) atomicAdd(&g_d[D_DEN], den_acc);
    for (int j = 0; j < 12; j++)
        atomicAdd(&g_d[D_OUT + kp * 192 + fbp + j], (double)po[j]);
}

// mincut numerator: sum_e w[e] * <ssm[row], ssm[col]>  (fp32 dot, fp64 reduce)
__global__ void k_num(const int* ei, const float* ew) {
    float acc = 0.f;
    for (int e = blockIdx.x * blockDim.x + threadIdx.x; e < NE;
         e += gridDim.x * blockDim.x) {
        int r = ei[e], c = ei[NE + e];
        const float4* a = (const float4*)&g_ssmf[r * 16];
        const float4* b = (const float4*)&g_ssmf[c * 16];
        float d = 0.f;
        #pragma unroll
        for (int i = 0; i < 4; i++) {
            float4 av = a[i], bv = b[i];
            d += av.x * bv.x + av.y * bv.y + av.z * bv.z + av.w * bv.w;
        }
        acc = fmaf(ew[e], d, acc);
    }
    __shared__ double red[256];
    red[threadIdx.x] = (double)acc; __syncthreads();
    for (int s = 128; s > 0; s >>= 1) {
        if (threadIdx.x < s) red[threadIdx.x] += red[threadIdx.x + s];
        __syncthreads();
    }
    if (threadIdx.x == 0) atomicAdd(&g_d[D_NUM], red[0]);
}

// ======= sort keys: fp32, 16-lane interleaved accumulation (FROZEN realization) ====
#define S2CH 512
__global__ void k_sub2v2(const float* SA) {
    __shared__ float sss[S2CH * 17];
    __shared__ float sa0[S2CH], sa1[S2CH];
    __shared__ float lr[2][16][17];
    int t = threadIdx.x;
    int k = t >> 4, lane = t & 15;
    int m0 = blockIdx.x, m1 = blockIdx.x + 128;
    float cs = (float)g_d[D_COLSUM + k];
    if (cs < 1e-12f) cs = 1e-12f;
    const float* sA0 = SA + (size_t)m0 * NN;
    const float* sA1 = SA + (size_t)m1 * NN;
    float acc0 = 0.f, acc1 = 0.f;
    for (int n0 = 0; n0 < NN; n0 += S2CH) {
        int span = NN - n0; if (span > S2CH) span = S2CH;
        __syncthreads();
        for (int i = t; i < span * 16; i += 256) {
            int n2 = i >> 4, kk = i & 15;
            sss[n2 * 17 + kk] = g_ssmf[(n0 + n2) * 16 + kk];
        }
        for (int i = t; i < span; i += 256) { sa0[i] = sA0[n0 + i]; sa1[i] = sA1[n0 + i]; }
        __syncthreads();
        for (int n2 = lane; n2 < span; n2 += 16) {
            float sv = sss[n2 * 17 + k];
            float tv = sv / cs;
            acc0 = fmaf(tv, sa0[n2], acc0);
            acc1 = fmaf(tv, sa1[n2], acc1);
        }
    }
    lr[0][k][lane] = acc0; lr[1][k][lane] = acc1;
    __syncthreads();
    for (int s = 8; s > 0; s >>= 1) {
        if (lane < s) {
            lr[0][k][lane] += lr[0][k][lane + s];
            lr[1][k][lane] += lr[1][k][lane + s];
        }
        __syncthreads();
    }
    if (lane == 0) {
        g_sub2f[k * 256 + m0] = lr[0][k][0];
        g_sub2f[k * 256 + m1] = lr[1][k][0];
    }
}

// losses (fp64) + out conversion
__global__ void k_fin(float* dout) {
    int t = threadIdx.x;
    __shared__ double red[256];
    __shared__ double fro;
    for (int idx = t; idx < 3072; idx += 256)
        g_outf[idx] = (float)g_d[D_OUT + idx];
    double v = g_d[D_SS + t];
    red[t] = v * v; __syncthreads();
    for (int s = 128; s > 0; s >>= 1) { if (t < s) red[t] += red[t + s]; __syncthreads(); }
    if (t == 0) fro = sqrt(red[0]);
    __syncthreads();
    double d = v / fro - (((t >> 4) == (t & 15)) ? 0.25 : 0.0);
    red[t] = d * d; __syncthreads();
    for (int s = 128; s > 0; s >>= 1) { if (t < s) red[t] += red[t + s]; __syncthreads(); }
    if (t == 0) {
        dout[16385] = (float)sqrt(red[0]);
        dout[16384] = (float)(-(g_d[D_NUM] / g_d[D_DEN]));
    }
}

// per-subgraph: stable sort clusters by fp32 score desc, emit emb row (fp32)
__global__ void k_embbuild() {
    __shared__ float rs[16];
    __shared__ int perm[16];
    int m = blockIdx.x, t = threadIdx.x;
    if (t < 16) rs[t] = g_sub2f[t * 256 + m];
    __syncthreads();
    if (t == 0) {
        int p[16];
        for (int i = 0; i < 16; i++) p[i] = i;
        for (int i = 1; i < 16; i++) {
            int key = p[i]; float kv = rs[key];
            int j = i - 1;
            while (j >= 0 && rs[p[j]] < kv) { p[j + 1] = p[j]; j--; }
            p[j + 1] = key;
        }
        for (int i = 0; i < 16; i++) perm[i] = p[i];
    }
    __syncthreads();
    for (int idx = t; idx < 3088; idx += 256) {
        int j = idx / 193, f = idx - j * 193;
        int pk = perm[j];
        g_emb[m * 3088 + idx] = (f < 192) ? g_outf[pk * 192 + f] : rs[pk];
    }
}

// MLP layer 1: 256x3088 @ 3088x128 fp32, split-K=16 with fp32 atomic accumulate
__global__ void k_mlp1(const float* W1) {
    int b = blockIdx.x;
    int rt = b & 7; b >>= 3; int ct = b & 1; int ks = b >> 1;
    int r0 = rt * 32, c0 = ct * 64, k0 = ks * 193;
    __shared__ float As[32][33];
    __shared__ float Bs[32][64];
    int t = threadIdx.x;
    int c = (t & 15) * 4, rr = (t >> 4) * 2;
    float acc[2][4] = {};
    for (int kk = 0; kk < 193; kk += 32) {
        int kc = 193 - kk; if (kc > 32) kc = 32;
        for (int i = t; i < 32 * 32; i += 256) {
            int r = i >> 5, kx = i & 31;
            As[r][kx] = (kx < kc) ? g_emb[(r0 + r) * 3088 + k0 + kk + kx] : 0.f;
        }
        for (int i = t; i < 32 * 64; i += 256) {
            int kx = i >> 6, cc = i & 63;
            Bs[kx][cc] = (kx < kc) ? W1[(k0 + kk + kx) * 128 + c0 + cc] : 0.f;
        }
        __syncthreads();
        #pragma unroll 8
        for (int kx = 0; kx < 32; kx++) {
            float4 bv = *(const float4*)&Bs[kx][c];
            float a0 = As[rr][kx], a1 = As[rr + 1][kx];
            acc[0][0] = fmaf(a0, bv.x, acc[0][0]); acc[0][1] = fmaf(a0, bv.y, acc[0][1]);
            acc[0][2] = fmaf(a0, bv.z, acc[0][2]); acc[0][3] = fmaf(a0, bv.w, acc[0][3]);
            acc[1][0] = fmaf(a1, bv.x, acc[1][0]); acc[1][1] = fmaf(a1, bv.y, acc[1][1]);
            acc[1][2] = fmaf(a1, bv.z, acc[1][2]); acc[1][3] = fmaf(a1, bv.w, acc[1][3]);
        }
        __syncthreads();
    }
    for (int i = 0; i < 2; i++)
        for (int j = 0; j < 4; j++)
            atomicAdd(&g_h1pre[(r0 + rr + i) * 128 + c0 + c + j], acc[i][j]);
}

__global__ void k_biasrelu(const float* b1) {
    int idx = blockIdx.x * blockDim.x + threadIdx.x;
    if (idx < 256 * 128)
        g_h1[idx] = fmaxf(g_h1pre[idx] + b1[idx & 127], 0.f);
}

// small dense layers fp32: 256x128 @ 128xCo
__global__ void k_mlps(const float* in, const float* W, const float* bias,
                       float* out, int Co, int dorelu) {
    __shared__ float As[32][129];
    __shared__ float Bs[128 * 32];
    int r0 = blockIdx.x * 32, c0 = blockIdx.y * 32;
    int t = threadIdx.x;
    for (int i = t; i < 32 * 128; i += 256) {
        int r = i >> 7, kx = i & 127;
        As[r][kx] = in[(r0 + r) * 128 + kx];
    }
    for (int i = t; i < 128 * 32; i += 256) {
        int kx = i >> 5, cc = i & 31;
        Bs[kx * 32 + cc] = W[kx * Co + c0 + cc];
    }
    __syncthreads();
    int r = t >> 3, c = (t & 7) * 4;
    float4 acc = { 0.f, 0.f, 0.f, 0.f };
    #pragma unroll 8
    for (int kx = 0; kx < 128; kx++) {
        float a = As[r][kx];
        float4 bv = *(const float4*)&Bs[kx * 32 + c];
        acc.x = fmaf(a, bv.x, acc.x); acc.y = fmaf(a, bv.y, acc.y);
        acc.z = fmaf(a, bv.z, acc.z); acc.w = fmaf(a, bv.w, acc.w);
    }
    float o0 = acc.x + bias[c0 + c + 0];
    float o1 = acc.y + bias[c0 + c + 1];
    float o2 = acc.z + bias[c0 + c + 2];
    float o3 = acc.w + bias[c0 + c + 3];
    if (dorelu) { o0 = fmaxf(o0, 0.f); o1 = fmaxf(o1, 0.f); o2 = fmaxf(o2, 0.f); o3 = fmaxf(o3, 0.f); }
    out[(r0 + r) * Co + c0 + c + 0] = o0;
    out[(r0 + r) * Co + c0 + c + 1] = o1;
    out[(r0 + r) * Co + c0 + c + 2] = o2;
    out[(r0 + r) * Co + c0 + c + 3] = o3;
}

// ---------------- launch ----------------
extern "C" void kernel_launch(void* const* d_in, const int* in_sizes, int n_in,
                              void* d_out, int out_size) {
    const int*   x    = (const int*)d_in[0];
    const int*   ei   = (const int*)d_in[1];
    const float* ew   = (const float*)d_in[2];
    const float* SA   = (const float*)d_in[4];
    const float* tab  = (const float*)d_in[5];
    const float* egw  = (const float*)d_in[6];
    const float* egb  = (const float*)d_in[7];
    const float* egm  = (const float*)d_in[8];
    const float* cW   = (const float*)d_in[9];
    const float* cB   = (const float*)d_in[10];
    const float* gnw  = (const float*)d_in[11];
    const float* gnb  = (const float*)d_in[12];
    const float* gnm  = (const float*)d_in[13];
    const float* glw  = (const float*)d_in[14];
    const float* glb  = (const float*)d_in[15];
    const float* glm  = (const float*)d_in[16];
    const float* sW   = (const float*)d_in[17];
    const float* sb   = (const float*)d_in[18];
    const float* pW1  = (const float*)d_in[19];
    const float* pb1  = (const float*)d_in[20];
    const float* pW2  = (const float*)d_in[21];
    const float* pb2  = (const float*)d_in[22];
    const float* pW3  = (const float*)d_in[23];
    const float* pb3  = (const float*)d_in[24];
    const float* pW4  = (const float*)d_in[25];
    const float* pb4  = (const float*)d_in[26];
    float* out = (float*)d_out;

    void *pv;
    float *E_p, *hcat_p, *h1p, *h2p, *h3p, *h1pre_p;
    double *degd_p, *d_p;
    int *cnt_p, *cur_p;
    cudaGetSymbolAddress(&pv, g_degd);    degd_p  = (double*)pv;
    cudaGetSymbolAddress(&pv, g_E);       E_p     = (float*)pv;
    cudaGetSymbolAddress(&pv, g_hcat);    hcat_p  = (float*)pv;
    cudaGetSymbolAddress(&pv, g_h1);      h1p     = (float*)pv;
    cudaGetSymbolAddress(&pv, g_h2);      h2p     = (float*)pv;
    cudaGetSymbolAddress(&pv, g_h3);      h3p     = (float*)pv;
    cudaGetSymbolAddress(&pv, g_h1pre);   h1pre_p = (float*)pv;
    cudaGetSymbolAddress(&pv, g_d);       d_p     = (double*)pv;
    cudaGetSymbolAddress(&pv, g_cnt);     cnt_p   = (int*)pv;
    cudaGetSymbolAddress(&pv, g_cur);     cur_p   = (int*)pv;

    cudaMemsetAsync(degd_p, 0, (size_t)NN * 8);
    cudaMemsetAsync(h1pre_p, 0, (size_t)256 * 128 * 4);
    cudaMemsetAsync(d_p, 0, (size_t)D_TOTAL * 8);
    cudaMemsetAsync(cnt_p, 0, (size_t)NN * 4);
    cudaMemsetAsync(cur_p, 0, (size_t)NN * 4);

    const double invN = 1.0 / (double)NN;

    k_deg<<<3125, 256>>>(ei, ew);
    k_norm<<<3125, 256>>>(ei, ew);
    k_scan1<<<49, 1024>>>();
    k_scan2<<<1, 64>>>();
    k_scan3<<<49, 1024>>>();
    k_scatter<<<3125, 256>>>(ei);
    k_rowsort<<<196, 256>>>();
    k_embed<<<256, 256>>>(x, tab);

    // layer 0
    k_lin<<<782, 256>>>(E_p, 64, d_p + D_EMB, egw, egb, egm, 0, cW, cB, invN);
    k_spmm_csr<<<400, 256>>>(0, d_p + D_G0, d_p + D_GL);
    // layer 1
    k_lin<<<782, 256>>>(hcat_p, 192, d_p + D_G0, gnw, gnb, gnm, 1, cW + 4096, cB + 64, invN);
    k_spmm_csr<<<400, 256>>>(64, d_p + D_G1, d_p + D_GL);
    // layer 2
    k_lin<<<782, 256>>>(hcat_p + 64, 192, d_p + D_G1, gnw + 64, gnb + 64, gnm + 64,
                        1, cW + 8192, cB + 128, invN);
    k_spmm_csr<<<400, 256>>>(128, (double*)0, d_p + D_GL);

    k_soft<<<256, 256>>>(sW, sb, d_p + D_GL, glw, glb, glm, invN);
    k_num<<<2048, 256>>>(ei, ew);
    k_sub2v2<<<128, 256>>>(SA);
    k_fin<<<1, 256>>>(out);
    k_embbuild<<<256, 256>>>();

    k_mlp1<<<256, 256>>>(pW1);
    k_biasrelu<<<128, 256>>>(pb1);
    k_mlps<<<dim3(8, 4), 256>>>(h1p, pW2, pb2, h2p, 128, 1);
    k_mlps<<<dim3(8, 4), 256>>>(h2p, pW3, pb3, h3p, 128, 1);
    k_mlps<<<dim3(8, 2), 256>>>(h3p, pW4, pb4, out, 64, 0);

    (void)in_sizes; (void)n_in; (void)out_size;
}